// round 3
// baseline (speedup 1.0000x reference)
#include <cuda_runtime.h>
#include <cuda_bf16.h>
#include <cstddef>

// Problem constants (fixed by the dataset)
#define cN 50000
#define cE 1600000
#define cD 128
#define SLOPE 0.01f

// ---------------- scratch (static device globals; no allocation) ----------------
__device__ int   g_outdeg[cN];
__device__ int   g_indeg[cN];
__device__ int   g_offsets[cN + 1];
__device__ int   g_cursor[cN];
__device__ int   g_blocksums[64];
__device__ int   g_csr[cE];
__device__ float g_norm_out[cN];
__device__ float g_norm_in[cN];
__device__ float g_agg[(size_t)cN * cD];
__device__ float g_h1[(size_t)cN * cD];
__device__ float g_h2[(size_t)cN * cD];
__device__ float g_s[cN];
__device__ float g_v100[100];

// ---------------- kernels ----------------

__global__ void k_zero() {
    int i = blockIdx.x * blockDim.x + threadIdx.x;
    int stride = gridDim.x * blockDim.x;
    for (; i < cN; i += stride) {
        g_outdeg[i] = 0;
        g_indeg[i] = 0;
        if (i < 100) g_v100[i] = 0.0f;
    }
}

__global__ void k_degrees(const int* __restrict__ src, const int* __restrict__ dst) {
    int i = blockIdx.x * blockDim.x + threadIdx.x;
    if (i < cE) {
        atomicAdd(&g_outdeg[src[i]], 1);
        atomicAdd(&g_indeg[dst[i]], 1);
    }
}

__global__ void k_norms() {
    int i = blockIdx.x * blockDim.x + threadIdx.x;
    if (i < cN) {
        g_norm_out[i] = rsqrtf(fmaxf((float)g_outdeg[i], 1.0f));
        g_norm_in[i]  = rsqrtf(fmaxf((float)g_indeg[i], 1.0f));
    }
}

// Block-level inclusive scan of in-degrees -> exclusive per-element into g_offsets,
// block totals into g_blocksums.
__global__ void k_scan_block() {
    __shared__ int sh[1024];
    int gid = blockIdx.x * 1024 + threadIdx.x;
    int v = (gid < cN) ? g_indeg[gid] : 0;
    sh[threadIdx.x] = v;
    __syncthreads();
    for (int off = 1; off < 1024; off <<= 1) {
        int t = (threadIdx.x >= off) ? sh[threadIdx.x - off] : 0;
        __syncthreads();
        sh[threadIdx.x] += t;
        __syncthreads();
    }
    if (gid < cN) g_offsets[gid] = sh[threadIdx.x] - v;   // exclusive within block
    if (threadIdx.x == 1023) g_blocksums[blockIdx.x] = sh[1023];
}

__global__ void k_scan_sums(int nb) {
    if (blockIdx.x == 0 && threadIdx.x == 0) {
        int run = 0;
        for (int i = 0; i < nb; i++) { int v = g_blocksums[i]; g_blocksums[i] = run; run += v; }
    }
}

__global__ void k_scan_add() {
    int gid = blockIdx.x * 1024 + threadIdx.x;
    if (gid < cN) {
        int o = g_offsets[gid] + g_blocksums[blockIdx.x];
        g_offsets[gid] = o;
        g_cursor[gid] = o;
    }
    if (gid == 0) g_offsets[cN] = cE;
}

__global__ void k_csr_fill(const int* __restrict__ src, const int* __restrict__ dst) {
    int i = blockIdx.x * blockDim.x + threadIdx.x;
    if (i < cE) {
        int p = atomicAdd(&g_cursor[dst[i]], 1);
        g_csr[p] = src[i];
    }
}

// One warp per node: gather rows of X (scaled by norm_out[src]) over in-edges,
// scale by norm_in[dst], write g_agg. Pure gather, no atomics.
__global__ void k_aggregate(const float* __restrict__ x_ext, int use_ext) {
    int gtid = blockIdx.x * blockDim.x + threadIdx.x;
    int node = gtid >> 5;
    int lane = gtid & 31;
    if (node >= cN) return;
    const float* __restrict__ X = use_ext ? x_ext : g_h1;
    int beg = g_offsets[node];
    int end = g_offsets[node + 1];
    float4 acc = make_float4(0.f, 0.f, 0.f, 0.f);
    for (int e = beg; e < end; e++) {
        int s = g_csr[e];
        float f = g_norm_out[s];
        float4 v = *(const float4*)&X[(size_t)s * cD + lane * 4];
        acc.x += f * v.x; acc.y += f * v.y; acc.z += f * v.z; acc.w += f * v.w;
    }
    float fi = g_norm_in[node];
    acc.x *= fi; acc.y *= fi; acc.z *= fi; acc.w *= fi;
    *(float4*)&g_agg[(size_t)node * cD + lane * 4] = acc;
}

// C = leaky?(g_agg @ W + bias)  -> g_h1 (layer1, with leaky) or g_h2 (layer2, linear)
// Block: 256 threads, tile 64 rows x 128 cols; thread computes 8 rows x 4 cols.
__global__ void k_gemm(const float* __restrict__ W, const float* __restrict__ bias,
                       int out_sel /* 1 -> g_h1 + leaky, 2 -> g_h2 */) {
    __shared__ float As[64][32];   // 8 KB
    __shared__ float Ws[32][128];  // 16 KB
    int tid  = threadIdx.x;
    int warp = tid >> 5;           // 0..7 : row group
    int lane = tid & 31;           // col group (4 cols each)
    int r0 = blockIdx.x * 64;
    float acc[8][4];
    #pragma unroll
    for (int i = 0; i < 8; i++)
        #pragma unroll
        for (int j = 0; j < 4; j++) acc[i][j] = 0.f;

    for (int k0 = 0; k0 < cD; k0 += 32) {
        // Load A panel: 64 rows x 32 cols = 512 float4
        #pragma unroll
        for (int i = tid; i < 512; i += 256) {
            int row = i >> 3, c4 = i & 7;
            float4 v = make_float4(0.f, 0.f, 0.f, 0.f);
            int gr = r0 + row;
            if (gr < cN) v = *(const float4*)&g_agg[(size_t)gr * cD + k0 + c4 * 4];
            *(float4*)&As[row][c4 * 4] = v;
        }
        // Load W panel: 32 rows x 128 cols = 1024 float4
        #pragma unroll
        for (int i = tid; i < 1024; i += 256) {
            int row = i >> 5, c4 = i & 31;
            *(float4*)&Ws[row][c4 * 4] = *(const float4*)&W[(size_t)(k0 + row) * cD + c4 * 4];
        }
        __syncthreads();
        #pragma unroll
        for (int k = 0; k < 32; k++) {
            float4 w4 = *(float4*)&Ws[k][lane * 4];
            #pragma unroll
            for (int i = 0; i < 8; i++) {
                float a = As[warp * 8 + i][k];
                acc[i][0] += a * w4.x; acc[i][1] += a * w4.y;
                acc[i][2] += a * w4.z; acc[i][3] += a * w4.w;
            }
        }
        __syncthreads();
    }

    float* C = (out_sel == 1) ? g_h1 : g_h2;
    int do_leaky = (out_sel == 1);
    float4 bv = *(const float4*)&bias[lane * 4];
    #pragma unroll
    for (int i = 0; i < 8; i++) {
        int r = r0 + warp * 8 + i;
        if (r < cN) {
            float4 o;
            o.x = acc[i][0] + bv.x; o.y = acc[i][1] + bv.y;
            o.z = acc[i][2] + bv.z; o.w = acc[i][3] + bv.w;
            if (do_leaky) {
                o.x = o.x >= 0.f ? o.x : SLOPE * o.x;
                o.y = o.y >= 0.f ? o.y : SLOPE * o.y;
                o.z = o.z >= 0.f ? o.z : SLOPE * o.z;
                o.w = o.w >= 0.f ? o.w : SLOPE * o.w;
            }
            *(float4*)&C[(size_t)r * cD + lane * 4] = o;
        }
    }
}

// g_s[i] = dot(g_h2[i,:], agg_w) + agg_b   (warp per row)
__global__ void k_rowdot(const float* __restrict__ agg_w, const float* __restrict__ agg_b) {
    int gtid = blockIdx.x * blockDim.x + threadIdx.x;
    int row = gtid >> 5;
    int lane = gtid & 31;
    if (row >= cN) return;
    float sum = 0.f;
    #pragma unroll
    for (int j = 0; j < 4; j++) {
        int c = lane + 32 * j;
        sum += g_h2[(size_t)row * cD + c] * agg_w[c];
    }
    #pragma unroll
    for (int o = 16; o; o >>= 1) sum += __shfl_xor_sync(0xFFFFFFFFu, sum, o);
    if (lane == 0) g_s[row] = sum + agg_b[0];
}

// g_v100[c] += sum_r g_s[r] * d1_w[r*100+c]   (partial per block, atomic finish)
__global__ void k_dense1(const float* __restrict__ d1_w) {
    int c = threadIdx.x;           // blockDim = 128, active c < 100
    int rows_per_block = (cN + gridDim.x - 1) / gridDim.x;
    int r0 = blockIdx.x * rows_per_block;
    int r1 = r0 + rows_per_block; if (r1 > cN) r1 = cN;
    if (c < 100) {
        float sum = 0.f;
        for (int r = r0; r < r1; r++)
            sum += g_s[r] * d1_w[(size_t)r * 100 + c];
        atomicAdd(&g_v100[c], sum);
    }
}

__global__ void k_final(const float* __restrict__ d1_b,
                        const float* __restrict__ d2_w, const float* __restrict__ d2_b,
                        const float* __restrict__ d3_w, const float* __restrict__ d3_b,
                        float* __restrict__ out) {
    __shared__ float h100[100];
    __shared__ float h20[20];
    int t = threadIdx.x; // 128
    if (t < 100) h100[t] = g_v100[t] + d1_b[t];
    __syncthreads();
    if (t < 20) {
        float v = d2_b[t];
        #pragma unroll 4
        for (int c = 0; c < 100; c++) v += h100[c] * d2_w[c * 20 + t];
        h20[t] = v >= 0.f ? v : SLOPE * v;
    }
    __syncthreads();
    if (t < 10) {
        float o = d3_b[t];
        #pragma unroll
        for (int c = 0; c < 20; c++) o += h20[c] * d3_w[c * 10 + t];
        out[t] = o;
    }
}

// ---------------- launch ----------------
extern "C" void kernel_launch(void* const* d_in, const int* in_sizes, int n_in,
                              void* d_out, int out_size) {
    const float* x     = (const float*)d_in[0];
    const int*   src   = (const int*)d_in[1];
    const int*   dst   = (const int*)d_in[2];
    const float* W1    = (const float*)d_in[3];
    const float* b1    = (const float*)d_in[4];
    const float* W2    = (const float*)d_in[5];
    const float* b2    = (const float*)d_in[6];
    const float* agg_w = (const float*)d_in[7];
    const float* agg_b = (const float*)d_in[8];
    const float* d1_w  = (const float*)d_in[9];
    const float* d1_b  = (const float*)d_in[10];
    const float* d2_w  = (const float*)d_in[11];
    const float* d2_b  = (const float*)d_in[12];
    const float* d3_w  = (const float*)d_in[13];
    const float* d3_b  = (const float*)d_in[14];
    float* out = (float*)d_out;

    const int nb_scan = (cN + 1023) / 1024;           // 49
    const int eb = (cE + 255) / 256;                  // 6250
    const int nbN = (cN + 255) / 256;                 // 196
    const int agg_blocks = (cN * 32 + 255) / 256;     // 6250 (warp per node)
    const int gemm_blocks = (cN + 63) / 64;           // 782

    k_zero<<<256, 256>>>();
    k_degrees<<<eb, 256>>>(src, dst);
    k_norms<<<nbN, 256>>>();
    k_scan_block<<<nb_scan, 1024>>>();
    k_scan_sums<<<1, 32>>>(nb_scan);
    k_scan_add<<<nb_scan, 1024>>>();
    k_csr_fill<<<eb, 256>>>(src, dst);

    // Layer 1
    k_aggregate<<<agg_blocks, 256>>>(x, 1);
    k_gemm<<<gemm_blocks, 256>>>(W1, b1, 1);
    // Layer 2
    k_aggregate<<<agg_blocks, 256>>>(x, 0);
    k_gemm<<<gemm_blocks, 256>>>(W2, b2, 2);

    // Head
    k_rowdot<<<agg_blocks, 256>>>(agg_w, agg_b);
    k_dense1<<<256, 128>>>(d1_w);
    k_final<<<1, 128>>>(d1_b, d2_w, d2_b, d3_w, d3_b, out);
}

// round 5
// speedup vs baseline: 1.0555x; 1.0555x over previous
#include <cuda_runtime.h>
#include <cuda_bf16.h>
#include <cstddef>

#define cN 50000
#define cE 1600000
#define cD 128
#define SLOPE 0.01f

// ---------------- scratch (static device globals; no allocation) ----------------
__device__ int   g_outdeg[cN];
__device__ int   g_indeg[cN];
__device__ int   g_offsets[cN + 1];
__device__ int   g_cursor[cN];
__device__ int   g_blocksums[64];
__device__ int   g_csr[cE];
__device__ float g_norm_out[cN];
__device__ float g_norm_in[cN];
__device__ float g_agg[(size_t)cN * cD];     // fp32 aggregate output (GEMM input)
__device__ short g_xq[(size_t)cN * cD];      // int16-quantized x (scaled rows)
__device__ short g_h1q[(size_t)cN * cD];     // int16-quantized h1
__device__ float g_xs[cN];                   // per-row scale * norm_out for x
__device__ float g_h1s[cN];                  // per-row scale * norm_out for h1
__device__ float g_s[cN];
__device__ float g_v100[100];

// ---------------- preprocessing ----------------

__global__ void k_zero() {
    int i = blockIdx.x * blockDim.x + threadIdx.x;
    int stride = gridDim.x * blockDim.x;
    for (; i < cN; i += stride) {
        g_outdeg[i] = 0;
        g_indeg[i] = 0;
        if (i < 100) g_v100[i] = 0.0f;
    }
}

__global__ void k_degrees(const int* __restrict__ src, const int* __restrict__ dst) {
    int i = blockIdx.x * blockDim.x + threadIdx.x;
    if (i < cE) {
        atomicAdd(&g_outdeg[src[i]], 1);
        atomicAdd(&g_indeg[dst[i]], 1);
    }
}

__global__ void k_scan_block() {
    __shared__ int sh[1024];
    int gid = blockIdx.x * 1024 + threadIdx.x;
    int v = (gid < cN) ? g_indeg[gid] : 0;
    sh[threadIdx.x] = v;
    __syncthreads();
    for (int off = 1; off < 1024; off <<= 1) {
        int t = (threadIdx.x >= off) ? sh[threadIdx.x - off] : 0;
        __syncthreads();
        sh[threadIdx.x] += t;
        __syncthreads();
    }
    if (gid < cN) g_offsets[gid] = sh[threadIdx.x] - v;   // exclusive within block
    if (threadIdx.x == 1023) g_blocksums[blockIdx.x] = sh[1023];
}

__global__ void k_scan_sums(int nb) {
    if (blockIdx.x == 0 && threadIdx.x == 0) {
        int run = 0;
        for (int i = 0; i < nb; i++) { int v = g_blocksums[i]; g_blocksums[i] = run; run += v; }
    }
}

// scan finalize + norms (fused)
__global__ void k_scan_add() {
    int gid = blockIdx.x * 1024 + threadIdx.x;
    if (gid < cN) {
        int o = g_offsets[gid] + g_blocksums[blockIdx.x];
        g_offsets[gid] = o;
        g_cursor[gid] = o;
        g_norm_out[gid] = rsqrtf(fmaxf((float)g_outdeg[gid], 1.0f));
        g_norm_in[gid]  = rsqrtf(fmaxf((float)g_indeg[gid], 1.0f));
    }
    if (gid == 0) g_offsets[cN] = cE;
}

__global__ void k_csr_fill(const int* __restrict__ src, const int* __restrict__ dst) {
    int i = blockIdx.x * blockDim.x + threadIdx.x;
    if (i < cE) {
        int p = atomicAdd(&g_cursor[dst[i]], 1);
        g_csr[p] = src[i];
    }
}

// Quantize x rows to int16 with per-row absmax scale; fold norm_out into the scale.
__global__ void k_quant_x(const float* __restrict__ x) {
    int gtid = blockIdx.x * blockDim.x + threadIdx.x;
    int row = gtid >> 5, lane = gtid & 31;
    if (row >= cN) return;
    float4 v = *(const float4*)&x[(size_t)row * cD + lane * 4];
    float m = fmaxf(fmaxf(fabsf(v.x), fabsf(v.y)), fmaxf(fabsf(v.z), fabsf(v.w)));
    #pragma unroll
    for (int off = 16; off; off >>= 1) m = fmaxf(m, __shfl_xor_sync(0xFFFFFFFFu, m, off));
    float inv = m > 0.f ? 32767.0f / m : 0.f;
    short4 q;
    q.x = (short)__float2int_rn(v.x * inv);
    q.y = (short)__float2int_rn(v.y * inv);
    q.z = (short)__float2int_rn(v.z * inv);
    q.w = (short)__float2int_rn(v.w * inv);
    *(short4*)&g_xq[(size_t)row * cD + lane * 4] = q;
    if (lane == 0) g_xs[row] = m * (1.0f / 32767.0f) * g_norm_out[row];
}

// ---------------- aggregation: warp-per-node int16 gather ----------------
__global__ void k_aggregate_q(int layer /*1: xq, 2: h1q*/) {
    int gtid = blockIdx.x * blockDim.x + threadIdx.x;
    int node = gtid >> 5, lane = gtid & 31;
    if (node >= cN) return;
    const short4* __restrict__ Xq = (layer == 1) ? (const short4*)g_xq : (const short4*)g_h1q;
    const float* __restrict__ S   = (layer == 1) ? g_xs : g_h1s;
    int beg = g_offsets[node];
    int end = g_offsets[node + 1];
    float4 acc = make_float4(0.f, 0.f, 0.f, 0.f);
    int e = beg;
    for (; e + 1 < end; e += 2) {
        int s0 = g_csr[e], s1 = g_csr[e + 1];
        float f0 = S[s0], f1 = S[s1];
        short4 v0 = Xq[(size_t)s0 * 32 + lane];
        short4 v1 = Xq[(size_t)s1 * 32 + lane];
        acc.x += f0 * (float)v0.x + f1 * (float)v1.x;
        acc.y += f0 * (float)v0.y + f1 * (float)v1.y;
        acc.z += f0 * (float)v0.z + f1 * (float)v1.z;
        acc.w += f0 * (float)v0.w + f1 * (float)v1.w;
    }
    if (e < end) {
        int s0 = g_csr[e];
        float f0 = S[s0];
        short4 v0 = Xq[(size_t)s0 * 32 + lane];
        acc.x += f0 * (float)v0.x;
        acc.y += f0 * (float)v0.y;
        acc.z += f0 * (float)v0.z;
        acc.w += f0 * (float)v0.w;
    }
    float fi = g_norm_in[node];
    acc.x *= fi; acc.y *= fi; acc.z *= fi; acc.w *= fi;
    *(float4*)&g_agg[(size_t)node * cD + lane * 4] = acc;
}

// ---------------- GEMM: g_agg[64x128 tile] @ W, packed f32x2 FFMA ----------------
// mode 1: leaky -> int16 quantize rows -> g_h1q/g_h1s (scale folds norm_out)
// mode 2: + b, rowdot with agg_w -> g_s
__global__ void k_gemm(const float* __restrict__ W, const float* __restrict__ bias,
                       const float* __restrict__ agg_w, const float* __restrict__ agg_b,
                       int mode) {
    __shared__ float AsT[32][66];   // k-major transposed A panel (+pad)
    __shared__ float Ws[32][128];
    int tid  = threadIdx.x;
    int warp = tid >> 5;            // 0..7: row group (8 rows)
    int lane = tid & 31;            // col group (4 cols)
    int r0 = blockIdx.x * 64;
    int warp8 = warp * 8;

    unsigned long long acc2[4][4];  // [rowpair][col], packed (row 2p, row 2p+1)
    #pragma unroll
    for (int p = 0; p < 4; p++)
        #pragma unroll
        for (int j = 0; j < 4; j++) acc2[p][j] = 0ull;

    for (int k0 = 0; k0 < cD; k0 += 32) {
        // A panel transposed: 64 rows x 32 k
        #pragma unroll
        for (int i = tid; i < 512; i += 256) {
            int row = i >> 3, c4 = i & 7;
            float4 v = make_float4(0.f, 0.f, 0.f, 0.f);
            int gr = r0 + row;
            if (gr < cN) v = *(const float4*)&g_agg[(size_t)gr * cD + k0 + c4 * 4];
            AsT[c4 * 4 + 0][row] = v.x;
            AsT[c4 * 4 + 1][row] = v.y;
            AsT[c4 * 4 + 2][row] = v.z;
            AsT[c4 * 4 + 3][row] = v.w;
        }
        // W panel: 32 k x 128 cols
        #pragma unroll
        for (int i = tid; i < 1024; i += 256) {
            int row = i >> 5, c4 = i & 31;
            *(float4*)&Ws[row][c4 * 4] = *(const float4*)&W[(size_t)(k0 + row) * cD + c4 * 4];
        }
        __syncthreads();
        #pragma unroll
        for (int k = 0; k < 32; k++) {
            float4 w = *(float4*)&Ws[k][lane * 4];
            unsigned long long w2[4];
            asm("mov.b64 %0, {%1, %1};" : "=l"(w2[0]) : "r"(__float_as_uint(w.x)));
            asm("mov.b64 %0, {%1, %1};" : "=l"(w2[1]) : "r"(__float_as_uint(w.y)));
            asm("mov.b64 %0, {%1, %1};" : "=l"(w2[2]) : "r"(__float_as_uint(w.z)));
            asm("mov.b64 %0, {%1, %1};" : "=l"(w2[3]) : "r"(__float_as_uint(w.w)));
            #pragma unroll
            for (int p = 0; p < 4; p++) {
                unsigned long long a2 = *(const unsigned long long*)&AsT[k][warp8 + 2 * p];
                asm("fma.rn.f32x2 %0, %1, %2, %3;" : "=l"(acc2[p][0]) : "l"(a2), "l"(w2[0]), "l"(acc2[p][0]));
                asm("fma.rn.f32x2 %0, %1, %2, %3;" : "=l"(acc2[p][1]) : "l"(a2), "l"(w2[1]), "l"(acc2[p][1]));
                asm("fma.rn.f32x2 %0, %1, %2, %3;" : "=l"(acc2[p][2]) : "l"(a2), "l"(w2[2]), "l"(acc2[p][2]));
                asm("fma.rn.f32x2 %0, %1, %2, %3;" : "=l"(acc2[p][3]) : "l"(a2), "l"(w2[3]), "l"(acc2[p][3]));
            }
        }
        __syncthreads();
    }

    float4 bv = *(const float4*)&bias[lane * 4];
    float bj[4] = {bv.x, bv.y, bv.z, bv.w};

    if (mode == 1) {
        // leaky + per-row int16 quantization
        #pragma unroll
        for (int p = 0; p < 4; p++) {
            #pragma unroll
            for (int half = 0; half < 2; half++) {
                int r = r0 + warp8 + 2 * p + half;
                float o[4];
                #pragma unroll
                for (int j = 0; j < 4; j++) {
                    unsigned long long v = acc2[p][j];
                    unsigned int bits = half ? (unsigned int)(v >> 32) : (unsigned int)v;
                    float f = __uint_as_float(bits) + bj[j];
                    o[j] = f >= 0.f ? f : SLOPE * f;
                }
                float m = fmaxf(fmaxf(fabsf(o[0]), fabsf(o[1])), fmaxf(fabsf(o[2]), fabsf(o[3])));
                #pragma unroll
                for (int off = 16; off; off >>= 1) m = fmaxf(m, __shfl_xor_sync(0xFFFFFFFFu, m, off));
                if (r < cN) {
                    float inv = m > 0.f ? 32767.0f / m : 0.f;
                    short4 q;
                    q.x = (short)__float2int_rn(o[0] * inv);
                    q.y = (short)__float2int_rn(o[1] * inv);
                    q.z = (short)__float2int_rn(o[2] * inv);
                    q.w = (short)__float2int_rn(o[3] * inv);
                    *(short4*)&g_h1q[(size_t)r * cD + lane * 4] = q;
                    if (lane == 0) g_h1s[r] = m * (1.0f / 32767.0f) * g_norm_out[r];
                }
            }
        }
    } else {
        // + bias, rowdot with agg_w -> g_s
        float4 aw = *(const float4*)&agg_w[lane * 4];
        float awj[4] = {aw.x, aw.y, aw.z, aw.w};
        float ab = agg_b[0];
        #pragma unroll
        for (int p = 0; p < 4; p++) {
            #pragma unroll
            for (int half = 0; half < 2; half++) {
                int r = r0 + warp8 + 2 * p + half;
                float sum = 0.f;
                #pragma unroll
                for (int j = 0; j < 4; j++) {
                    unsigned long long v = acc2[p][j];
                    unsigned int bits = half ? (unsigned int)(v >> 32) : (unsigned int)v;
                    sum += (__uint_as_float(bits) + bj[j]) * awj[j];
                }
                #pragma unroll
                for (int off = 16; off; off >>= 1) sum += __shfl_xor_sync(0xFFFFFFFFu, sum, off);
                if (r < cN && lane == 0) g_s[r] = sum + ab;
            }
        }
    }
}

// ---------------- head ----------------
__global__ void k_dense1(const float* __restrict__ d1_w) {
    int c = threadIdx.x;           // blockDim = 128, active c < 100
    int rows_per_block = (cN + gridDim.x - 1) / gridDim.x;
    int r0 = blockIdx.x * rows_per_block;
    int r1 = r0 + rows_per_block; if (r1 > cN) r1 = cN;
    if (c < 100) {
        float sum = 0.f;
        for (int r = r0; r < r1; r++)
            sum += g_s[r] * d1_w[(size_t)r * 100 + c];
        atomicAdd(&g_v100[c], sum);
    }
}

__global__ void k_final(const float* __restrict__ d1_b,
                        const float* __restrict__ d2_w, const float* __restrict__ d2_b,
                        const float* __restrict__ d3_w, const float* __restrict__ d3_b,
                        float* __restrict__ out) {
    __shared__ float h100[100];
    __shared__ float h20[20];
    int t = threadIdx.x; // 128
    if (t < 100) h100[t] = g_v100[t] + d1_b[t];
    __syncthreads();
    if (t < 20) {
        float v = d2_b[t];
        #pragma unroll 4
        for (int c = 0; c < 100; c++) v += h100[c] * d2_w[c * 20 + t];
        h20[t] = v >= 0.f ? v : SLOPE * v;
    }
    __syncthreads();
    if (t < 10) {
        float o = d3_b[t];
        #pragma unroll
        for (int c = 0; c < 20; c++) o += h20[c] * d3_w[c * 10 + t];
        out[t] = o;
    }
}

// ---------------- launch ----------------
extern "C" void kernel_launch(void* const* d_in, const int* in_sizes, int n_in,
                              void* d_out, int out_size) {
    const float* x     = (const float*)d_in[0];
    const int*   src   = (const int*)d_in[1];
    const int*   dst   = (const int*)d_in[2];
    const float* W1    = (const float*)d_in[3];
    const float* b1    = (const float*)d_in[4];
    const float* W2    = (const float*)d_in[5];
    const float* b2    = (const float*)d_in[6];
    const float* agg_w = (const float*)d_in[7];
    const float* agg_b = (const float*)d_in[8];
    const float* d1_w  = (const float*)d_in[9];
    const float* d1_b  = (const float*)d_in[10];
    const float* d2_w  = (const float*)d_in[11];
    const float* d2_b  = (const float*)d_in[12];
    const float* d3_w  = (const float*)d_in[13];
    const float* d3_b  = (const float*)d_in[14];
    float* out = (float*)d_out;

    const int nb_scan = (cN + 1023) / 1024;           // 49
    const int eb = (cE + 255) / 256;                  // 6250
    const int warp_blocks = (cN * 32 + 255) / 256;    // 6250 (warp per node/row)
    const int gemm_blocks = (cN + 63) / 64;           // 782

    k_zero<<<256, 256>>>();
    k_degrees<<<eb, 256>>>(src, dst);
    k_scan_block<<<nb_scan, 1024>>>();
    k_scan_sums<<<1, 32>>>(nb_scan);
    k_scan_add<<<nb_scan, 1024>>>();
    k_csr_fill<<<eb, 256>>>(src, dst);
    k_quant_x<<<warp_blocks, 256>>>(x);

    // Layer 1
    k_aggregate_q<<<warp_blocks, 256>>>(1);
    k_gemm<<<gemm_blocks, 256>>>(W1, b1, agg_w, agg_b, 1);
    // Layer 2
    k_aggregate_q<<<warp_blocks, 256>>>(2);
    k_gemm<<<gemm_blocks, 256>>>(W2, b2, agg_w, agg_b, 2);

    // Head
    k_dense1<<<256, 128>>>(d1_w);
    k_final<<<1, 128>>>(d1_b, d2_w, d2_b, d3_w, d3_b, out);
}

// round 6
// speedup vs baseline: 1.4356x; 1.3601x over previous
#include <cuda_runtime.h>
#include <cuda_bf16.h>
#include <cstddef>

#define cN 50000
#define cE 1600000
#define cD 128
#define SLOPE 0.01f

// ---------------- scratch (static device globals; no allocation) ----------------
__device__ int   g_outdeg[cN];
__device__ int   g_indeg[cN];
__device__ int   g_offsets[cN + 1];
__device__ int   g_cursor[cN];
__device__ int   g_blocksums[64];
__device__ int   g_csr[cE];
__device__ float g_norm_out[cN];
__device__ float g_norm_in[cN];
__device__ float g_agg[(size_t)cN * cD];     // fp32 aggregate output (GEMM input)
__device__ short g_xq[(size_t)cN * cD];      // int16-quantized x (scaled rows)
__device__ float g_xs[cN];                   // per-row scale * norm_out for x
__device__ float g_t[cN];                    // t[r] = norm_out[r] * dot(h1[r], u)
__device__ float g_u[cD];                    // u = W2 @ agg_w
__device__ float g_c;                        // c = b2 . agg_w + agg_b
__device__ float g_s[cN];
__device__ float g_v100[100];

// ---------------- preprocessing ----------------

__global__ void k_zero() {
    int i = blockIdx.x * blockDim.x + threadIdx.x;
    int stride = gridDim.x * blockDim.x;
    for (; i < cN; i += stride) {
        g_outdeg[i] = 0;
        g_indeg[i] = 0;
        if (i < 100) g_v100[i] = 0.0f;
    }
}

__global__ void k_degrees(const int* __restrict__ src, const int* __restrict__ dst) {
    int i = blockIdx.x * blockDim.x + threadIdx.x;
    if (i < cE) {
        atomicAdd(&g_outdeg[src[i]], 1);
        atomicAdd(&g_indeg[dst[i]], 1);
    }
}

// Block-level inclusive scan of in-degrees; per-block totals into g_blocksums.
__global__ void k_scan_block() {
    __shared__ int sh[1024];
    int gid = blockIdx.x * 1024 + threadIdx.x;
    int v = (gid < cN) ? g_indeg[gid] : 0;
    sh[threadIdx.x] = v;
    __syncthreads();
    for (int off = 1; off < 1024; off <<= 1) {
        int t = (threadIdx.x >= off) ? sh[threadIdx.x - off] : 0;
        __syncthreads();
        sh[threadIdx.x] += t;
        __syncthreads();
    }
    if (gid < cN) g_offsets[gid] = sh[threadIdx.x] - v;   // exclusive within block
    if (threadIdx.x == 1023) g_blocksums[blockIdx.x] = sh[1023];
}

// Fused: per-block base (redundant reduce over prior block sums) + finalize + norms.
__global__ void k_scan_add() {
    __shared__ int s_base;
    if (threadIdx.x < 32) {
        int v = 0;
        for (int i = threadIdx.x; i < blockIdx.x; i += 32) v += g_blocksums[i];
        #pragma unroll
        for (int o = 16; o; o >>= 1) v += __shfl_xor_sync(0xFFFFFFFFu, v, o);
        if (threadIdx.x == 0) s_base = v;
    }
    __syncthreads();
    int gid = blockIdx.x * 1024 + threadIdx.x;
    if (gid < cN) {
        int o = g_offsets[gid] + s_base;
        g_offsets[gid] = o;
        g_cursor[gid] = o;
        g_norm_out[gid] = rsqrtf(fmaxf((float)g_outdeg[gid], 1.0f));
        g_norm_in[gid]  = rsqrtf(fmaxf((float)g_indeg[gid], 1.0f));
    }
    if (gid == 0) g_offsets[cN] = cE;
}

__global__ void k_csr_fill(const int* __restrict__ src, const int* __restrict__ dst) {
    int i = blockIdx.x * blockDim.x + threadIdx.x;
    if (i < cE) {
        int p = atomicAdd(&g_cursor[dst[i]], 1);
        g_csr[p] = src[i];
    }
}

// Quantize x rows to int16 with per-row absmax scale; fold norm_out into the scale.
__global__ void k_quant_x(const float* __restrict__ x) {
    int gtid = blockIdx.x * blockDim.x + threadIdx.x;
    int row = gtid >> 5, lane = gtid & 31;
    if (row >= cN) return;
    float4 v = *(const float4*)&x[(size_t)row * cD + lane * 4];
    float m = fmaxf(fmaxf(fabsf(v.x), fabsf(v.y)), fmaxf(fabsf(v.z), fabsf(v.w)));
    #pragma unroll
    for (int off = 16; off; off >>= 1) m = fmaxf(m, __shfl_xor_sync(0xFFFFFFFFu, m, off));
    float inv = m > 0.f ? 32767.0f / m : 0.f;
    short4 q;
    q.x = (short)__float2int_rn(v.x * inv);
    q.y = (short)__float2int_rn(v.y * inv);
    q.z = (short)__float2int_rn(v.z * inv);
    q.w = (short)__float2int_rn(v.w * inv);
    *(short4*)&g_xq[(size_t)row * cD + lane * 4] = q;
    if (lane == 0) g_xs[row] = m * (1.0f / 32767.0f) * g_norm_out[row];
}

// u = W2 @ agg_w  (warp per row), c = b2 . agg_w + agg_b
__global__ void k_u(const float* __restrict__ W2, const float* __restrict__ agg_w,
                    const float* __restrict__ b2, const float* __restrict__ agg_b) {
    int gtid = blockIdx.x * blockDim.x + threadIdx.x;
    int w = gtid >> 5, lane = gtid & 31;
    if (w < cD) {
        float sum = 0.f;
        #pragma unroll
        for (int c = lane; c < cD; c += 32) sum += W2[(size_t)w * cD + c] * agg_w[c];
        #pragma unroll
        for (int o = 16; o; o >>= 1) sum += __shfl_xor_sync(0xFFFFFFFFu, sum, o);
        if (lane == 0) g_u[w] = sum;
    } else if (w == cD) {
        float sum = 0.f;
        #pragma unroll
        for (int c = lane; c < cD; c += 32) sum += b2[c] * agg_w[c];
        #pragma unroll
        for (int o = 16; o; o >>= 1) sum += __shfl_xor_sync(0xFFFFFFFFu, sum, o);
        if (lane == 0) g_c = sum + agg_b[0];
    }
}

// ---------------- aggregation (layer 1 only): warp-per-node int16 gather ----------------
__global__ void k_aggregate_q() {
    int gtid = blockIdx.x * blockDim.x + threadIdx.x;
    int node = gtid >> 5, lane = gtid & 31;
    if (node >= cN) return;
    const short4* __restrict__ Xq = (const short4*)g_xq;
    int beg = g_offsets[node];
    int end = g_offsets[node + 1];
    float4 acc = make_float4(0.f, 0.f, 0.f, 0.f);
    int e = beg;
    for (; e + 1 < end; e += 2) {
        int s0 = g_csr[e], s1 = g_csr[e + 1];
        float f0 = g_xs[s0], f1 = g_xs[s1];
        short4 v0 = Xq[(size_t)s0 * 32 + lane];
        short4 v1 = Xq[(size_t)s1 * 32 + lane];
        acc.x += f0 * (float)v0.x + f1 * (float)v1.x;
        acc.y += f0 * (float)v0.y + f1 * (float)v1.y;
        acc.z += f0 * (float)v0.z + f1 * (float)v1.z;
        acc.w += f0 * (float)v0.w + f1 * (float)v1.w;
    }
    if (e < end) {
        int s0 = g_csr[e];
        float f0 = g_xs[s0];
        short4 v0 = Xq[(size_t)s0 * 32 + lane];
        acc.x += f0 * (float)v0.x;
        acc.y += f0 * (float)v0.y;
        acc.z += f0 * (float)v0.z;
        acc.w += f0 * (float)v0.w;
    }
    float fi = g_norm_in[node];
    acc.x *= fi; acc.y *= fi; acc.z *= fi; acc.w *= fi;
    *(float4*)&g_agg[(size_t)node * cD + lane * 4] = acc;
}

// ---------------- GEMM1: g_agg @ W1 + b1 -> leaky -> dot with u -> g_t ----------------
// Block: 256 threads, tile 64 rows x 128 cols; packed f32x2 FFMA mainloop.
// h1 never leaves registers.
__global__ void k_gemm(const float* __restrict__ W, const float* __restrict__ bias) {
    __shared__ float AsT[32][66];   // k-major transposed A panel (+pad)
    __shared__ float Ws[32][128];
    int tid  = threadIdx.x;
    int warp = tid >> 5;            // 0..7: row group (8 rows)
    int lane = tid & 31;            // col group (4 cols)
    int r0 = blockIdx.x * 64;
    int warp8 = warp * 8;

    unsigned long long acc2[4][4];  // [rowpair][col], packed (row 2p, row 2p+1)
    #pragma unroll
    for (int p = 0; p < 4; p++)
        #pragma unroll
        for (int j = 0; j < 4; j++) acc2[p][j] = 0ull;

    for (int k0 = 0; k0 < cD; k0 += 32) {
        #pragma unroll
        for (int i = tid; i < 512; i += 256) {
            int row = i >> 3, c4 = i & 7;
            float4 v = make_float4(0.f, 0.f, 0.f, 0.f);
            int gr = r0 + row;
            if (gr < cN) v = *(const float4*)&g_agg[(size_t)gr * cD + k0 + c4 * 4];
            AsT[c4 * 4 + 0][row] = v.x;
            AsT[c4 * 4 + 1][row] = v.y;
            AsT[c4 * 4 + 2][row] = v.z;
            AsT[c4 * 4 + 3][row] = v.w;
        }
        #pragma unroll
        for (int i = tid; i < 1024; i += 256) {
            int row = i >> 5, c4 = i & 31;
            *(float4*)&Ws[row][c4 * 4] = *(const float4*)&W[(size_t)(k0 + row) * cD + c4 * 4];
        }
        __syncthreads();
        #pragma unroll
        for (int k = 0; k < 32; k++) {
            float4 w = *(float4*)&Ws[k][lane * 4];
            unsigned long long w2[4];
            asm("mov.b64 %0, {%1, %1};" : "=l"(w2[0]) : "r"(__float_as_uint(w.x)));
            asm("mov.b64 %0, {%1, %1};" : "=l"(w2[1]) : "r"(__float_as_uint(w.y)));
            asm("mov.b64 %0, {%1, %1};" : "=l"(w2[2]) : "r"(__float_as_uint(w.z)));
            asm("mov.b64 %0, {%1, %1};" : "=l"(w2[3]) : "r"(__float_as_uint(w.w)));
            #pragma unroll
            for (int p = 0; p < 4; p++) {
                unsigned long long a2 = *(const unsigned long long*)&AsT[k][warp8 + 2 * p];
                asm("fma.rn.f32x2 %0, %1, %2, %3;" : "=l"(acc2[p][0]) : "l"(a2), "l"(w2[0]), "l"(acc2[p][0]));
                asm("fma.rn.f32x2 %0, %1, %2, %3;" : "=l"(acc2[p][1]) : "l"(a2), "l"(w2[1]), "l"(acc2[p][1]));
                asm("fma.rn.f32x2 %0, %1, %2, %3;" : "=l"(acc2[p][2]) : "l"(a2), "l"(w2[2]), "l"(acc2[p][2]));
                asm("fma.rn.f32x2 %0, %1, %2, %3;" : "=l"(acc2[p][3]) : "l"(a2), "l"(w2[3]), "l"(acc2[p][3]));
            }
        }
        __syncthreads();
    }

    float4 bv = *(const float4*)&bias[lane * 4];
    float bj[4] = {bv.x, bv.y, bv.z, bv.w};
    float4 uv = *(const float4*)&g_u[lane * 4];
    float uj[4] = {uv.x, uv.y, uv.z, uv.w};

    // Epilogue: leaky(h1 row) . u, scaled by norm_out -> g_t[r]
    #pragma unroll
    for (int p = 0; p < 4; p++) {
        #pragma unroll
        for (int half = 0; half < 2; half++) {
            int r = r0 + warp8 + 2 * p + half;
            float sum = 0.f;
            #pragma unroll
            for (int j = 0; j < 4; j++) {
                unsigned long long v = acc2[p][j];
                unsigned int bits = half ? (unsigned int)(v >> 32) : (unsigned int)v;
                float f = __uint_as_float(bits) + bj[j];
                f = f >= 0.f ? f : SLOPE * f;
                sum += f * uj[j];
            }
            #pragma unroll
            for (int off = 16; off; off >>= 1) sum += __shfl_xor_sync(0xFFFFFFFFu, sum, off);
            if (r < cN && lane == 0) g_t[r] = sum * g_norm_out[r];
        }
    }
}

// ---------------- layer 2 (collapsed): scalar edge gather ----------------
// s[i] = norm_in[i] * sum_{e in in(i)} t[csr[e]] + c
__global__ void k_sgather() {
    int gtid = blockIdx.x * blockDim.x + threadIdx.x;
    int node = gtid >> 5, lane = gtid & 31;
    if (node >= cN) return;
    int beg = g_offsets[node];
    int end = g_offsets[node + 1];
    float sum = 0.f;
    for (int e = beg + lane; e < end; e += 32) sum += g_t[g_csr[e]];
    #pragma unroll
    for (int o = 16; o; o >>= 1) sum += __shfl_xor_sync(0xFFFFFFFFu, sum, o);
    if (lane == 0) g_s[node] = sum * g_norm_in[node] + g_c;
}

// ---------------- head ----------------
__global__ void k_dense1(const float* __restrict__ d1_w) {
    int c = threadIdx.x;           // blockDim = 128, active c < 100
    int rows_per_block = (cN + gridDim.x - 1) / gridDim.x;
    int r0 = blockIdx.x * rows_per_block;
    int r1 = r0 + rows_per_block; if (r1 > cN) r1 = cN;
    if (c < 100) {
        float sum = 0.f;
        for (int r = r0; r < r1; r++)
            sum += g_s[r] * d1_w[(size_t)r * 100 + c];
        atomicAdd(&g_v100[c], sum);
    }
}

__global__ void k_final(const float* __restrict__ d1_b,
                        const float* __restrict__ d2_w, const float* __restrict__ d2_b,
                        const float* __restrict__ d3_w, const float* __restrict__ d3_b,
                        float* __restrict__ out) {
    __shared__ float h100[100];
    __shared__ float h20[20];
    int t = threadIdx.x; // 128
    if (t < 100) h100[t] = g_v100[t] + d1_b[t];
    __syncthreads();
    if (t < 20) {
        float v = d2_b[t];
        #pragma unroll 4
        for (int c = 0; c < 100; c++) v += h100[c] * d2_w[c * 20 + t];
        h20[t] = v >= 0.f ? v : SLOPE * v;
    }
    __syncthreads();
    if (t < 10) {
        float o = d3_b[t];
        #pragma unroll
        for (int c = 0; c < 20; c++) o += h20[c] * d3_w[c * 10 + t];
        out[t] = o;
    }
}

// ---------------- launch ----------------
extern "C" void kernel_launch(void* const* d_in, const int* in_sizes, int n_in,
                              void* d_out, int out_size) {
    const float* x     = (const float*)d_in[0];
    const int*   src   = (const int*)d_in[1];
    const int*   dst   = (const int*)d_in[2];
    const float* W1    = (const float*)d_in[3];
    const float* b1    = (const float*)d_in[4];
    const float* W2    = (const float*)d_in[5];
    const float* b2    = (const float*)d_in[6];
    const float* agg_w = (const float*)d_in[7];
    const float* agg_b = (const float*)d_in[8];
    const float* d1_w  = (const float*)d_in[9];
    const float* d1_b  = (const float*)d_in[10];
    const float* d2_w  = (const float*)d_in[11];
    const float* d2_b  = (const float*)d_in[12];
    const float* d3_w  = (const float*)d_in[13];
    const float* d3_b  = (const float*)d_in[14];
    float* out = (float*)d_out;

    const int nb_scan = (cN + 1023) / 1024;           // 49
    const int eb = (cE + 255) / 256;                  // 6250
    const int warp_blocks = (cN * 32 + 255) / 256;    // 6250 (warp per node/row)
    const int gemm_blocks = (cN + 63) / 64;           // 782
    const int u_blocks = ((cD + 1) * 32 + 255) / 256; // 17

    k_zero<<<256, 256>>>();
    k_degrees<<<eb, 256>>>(src, dst);
    k_scan_block<<<nb_scan, 1024>>>();
    k_scan_add<<<nb_scan, 1024>>>();
    k_csr_fill<<<eb, 256>>>(src, dst);
    k_quant_x<<<warp_blocks, 256>>>(x);
    k_u<<<u_blocks, 256>>>(W2, agg_w, b2, agg_b);

    k_aggregate_q<<<warp_blocks, 256>>>();
    k_gemm<<<gemm_blocks, 256>>>(W1, b1);
    k_sgather<<<warp_blocks, 256>>>();

    k_dense1<<<256, 128>>>(d1_w);
    k_final<<<1, 128>>>(d1_b, d2_w, d2_b, d3_w, d3_b, out);
}

// round 7
// speedup vs baseline: 1.7668x; 1.2307x over previous
#include <cuda_runtime.h>
#include <cuda_bf16.h>
#include <cstddef>
#include <cstdint>

#define cN 50000
#define cE 1600000
#define cD 128
#define SLOPE 0.01f

// ---------------- scratch (static device globals; no allocation) ----------------
__device__ int   g_outdeg[cN];
__device__ int   g_indeg[cN];
__device__ int   g_offsets[cN + 1];
__device__ int   g_cursor[cN];
__device__ int   g_blocksums[64];
__device__ int   g_csr[cE];
__device__ float g_norm_out[cN];
__device__ float g_norm_in[cN];
__device__ short g_yq[(size_t)cN * cD];      // int16-quantized y = x@W1 (per-row scale)
__device__ float g_ys[cN];                   // per-row scale for y (absmax/32767)
__device__ float g_t[cN];                    // t[r] = norm_out[r] * dot(leaky(h1[r]), u)
__device__ float g_u[cD];                    // u = W2 @ agg_w
__device__ float g_c;                        // c = b2 . agg_w + agg_b
__device__ float g_s[cN];
__device__ float g_v100[100];

// ---------------- preprocessing ----------------

__global__ void k_zero() {
    int i = blockIdx.x * blockDim.x + threadIdx.x;
    int stride = gridDim.x * blockDim.x;
    for (; i < cN; i += stride) {
        g_outdeg[i] = 0;
        g_indeg[i] = 0;
        if (i < 100) g_v100[i] = 0.0f;
    }
}

__global__ void k_degrees(const int* __restrict__ src, const int* __restrict__ dst) {
    int i = blockIdx.x * blockDim.x + threadIdx.x;
    if (i < cE) {
        atomicAdd(&g_outdeg[src[i]], 1);
        atomicAdd(&g_indeg[dst[i]], 1);
    }
}

__global__ void k_scan_block() {
    __shared__ int sh[1024];
    int gid = blockIdx.x * 1024 + threadIdx.x;
    int v = (gid < cN) ? g_indeg[gid] : 0;
    sh[threadIdx.x] = v;
    __syncthreads();
    for (int off = 1; off < 1024; off <<= 1) {
        int t = (threadIdx.x >= off) ? sh[threadIdx.x - off] : 0;
        __syncthreads();
        sh[threadIdx.x] += t;
        __syncthreads();
    }
    if (gid < cN) g_offsets[gid] = sh[threadIdx.x] - v;   // exclusive within block
    if (threadIdx.x == 1023) g_blocksums[blockIdx.x] = sh[1023];
}

// per-block base + finalize + norms (fused)
__global__ void k_scan_add() {
    __shared__ int s_base;
    if (threadIdx.x < 32) {
        int v = 0;
        for (int i = threadIdx.x; i < blockIdx.x; i += 32) v += g_blocksums[i];
        #pragma unroll
        for (int o = 16; o; o >>= 1) v += __shfl_xor_sync(0xFFFFFFFFu, v, o);
        if (threadIdx.x == 0) s_base = v;
    }
    __syncthreads();
    int gid = blockIdx.x * 1024 + threadIdx.x;
    if (gid < cN) {
        int o = g_offsets[gid] + s_base;
        g_offsets[gid] = o;
        g_cursor[gid] = o;
        g_norm_out[gid] = rsqrtf(fmaxf((float)g_outdeg[gid], 1.0f));
        g_norm_in[gid]  = rsqrtf(fmaxf((float)g_indeg[gid], 1.0f));
    }
    if (gid == 0) g_offsets[cN] = cE;
}

__global__ void k_csr_fill(const int* __restrict__ src, const int* __restrict__ dst) {
    int i = blockIdx.x * blockDim.x + threadIdx.x;
    if (i < cE) {
        int p = atomicAdd(&g_cursor[dst[i]], 1);
        g_csr[p] = src[i];
    }
}

// u = W2 @ agg_w  (warp per row), c = b2 . agg_w + agg_b
__global__ void k_u(const float* __restrict__ W2, const float* __restrict__ agg_w,
                    const float* __restrict__ b2, const float* __restrict__ agg_b) {
    int gtid = blockIdx.x * blockDim.x + threadIdx.x;
    int w = gtid >> 5, lane = gtid & 31;
    if (w < cD) {
        float sum = 0.f;
        #pragma unroll
        for (int c = lane; c < cD; c += 32) sum += W2[(size_t)w * cD + c] * agg_w[c];
        #pragma unroll
        for (int o = 16; o; o >>= 1) sum += __shfl_xor_sync(0xFFFFFFFFu, sum, o);
        if (lane == 0) g_u[w] = sum;
    } else if (w == cD) {
        float sum = 0.f;
        #pragma unroll
        for (int c = lane; c < cD; c += 32) sum += b2[c] * agg_w[c];
        #pragma unroll
        for (int o = 16; o; o >>= 1) sum += __shfl_xor_sync(0xFFFFFFFFu, sum, o);
        if (lane == 0) g_c = sum + agg_b[0];
    }
}

// ---------------- y = x @ W1 via tf32 tensor cores, int16-quantized epilogue ----------------
// Block: 256 threads, tile 128 rows x 128 cols, K paneled by 32.
// Warp w owns rows [w*16, w*16+16), full 128 cols: 16 n-tiles of m16n8k8.
__device__ __forceinline__ uint32_t f2tf32(float f) {
    uint32_t u;
    asm("cvt.rna.tf32.f32 %0, %1;" : "=r"(u) : "f"(f));
    return u;
}

__global__ __launch_bounds__(256) void k_gemm_y(const float* __restrict__ x,
                                                const float* __restrict__ W1) {
    __shared__ uint32_t As[128 * 36];   // row-major, stride 36 (bank-conflict-free frags)
    __shared__ uint32_t Ws[32 * 132];   // k-major, stride 132
    int tid = threadIdx.x;
    int wid = tid >> 5;
    int lane = tid & 31;
    int r0 = blockIdx.x * 128;

    float acc[16][4];
    #pragma unroll
    for (int nt = 0; nt < 16; nt++)
        #pragma unroll
        for (int j = 0; j < 4; j++) acc[nt][j] = 0.f;

    for (int k0 = 0; k0 < cD; k0 += 32) {
        // A panel: 128 rows x 32 cols (1024 float4 loads over 256 threads)
        #pragma unroll
        for (int i = 0; i < 4; i++) {
            int idx = tid + 256 * i;
            int row = idx >> 3, c4 = idx & 7;
            int gr = r0 + row;
            float4 v = make_float4(0.f, 0.f, 0.f, 0.f);
            if (gr < cN) v = *(const float4*)&x[(size_t)gr * cD + k0 + c4 * 4];
            uint32_t* p = &As[row * 36 + c4 * 4];
            p[0] = f2tf32(v.x); p[1] = f2tf32(v.y); p[2] = f2tf32(v.z); p[3] = f2tf32(v.w);
        }
        // W panel: 32 k x 128 cols
        #pragma unroll
        for (int i = 0; i < 4; i++) {
            int idx = tid + 256 * i;
            int row = idx >> 5, c4 = idx & 31;
            float4 v = *(const float4*)&W1[(size_t)(k0 + row) * cD + c4 * 4];
            uint32_t* p = &Ws[row * 132 + c4 * 4];
            p[0] = f2tf32(v.x); p[1] = f2tf32(v.y); p[2] = f2tf32(v.z); p[3] = f2tf32(v.w);
        }
        __syncthreads();
        #pragma unroll
        for (int ks = 0; ks < 4; ks++) {
            int ar = wid * 16 + (lane >> 2);
            int ac = ks * 8 + (lane & 3);
            uint32_t a0 = As[ar * 36 + ac];
            uint32_t a1 = As[(ar + 8) * 36 + ac];
            uint32_t a2 = As[ar * 36 + ac + 4];
            uint32_t a3 = As[(ar + 8) * 36 + ac + 4];
            int bk = ks * 8 + (lane & 3);
            int bn0 = (lane >> 2);
            #pragma unroll
            for (int nt = 0; nt < 16; nt++) {
                uint32_t b0 = Ws[bk * 132 + nt * 8 + bn0];
                uint32_t b1 = Ws[(bk + 4) * 132 + nt * 8 + bn0];
                asm volatile(
                    "mma.sync.aligned.m16n8k8.row.col.f32.tf32.tf32.f32 "
                    "{%0,%1,%2,%3}, {%4,%5,%6,%7}, {%8,%9}, {%0,%1,%2,%3};"
                    : "+f"(acc[nt][0]), "+f"(acc[nt][1]), "+f"(acc[nt][2]), "+f"(acc[nt][3])
                    : "r"(a0), "r"(a1), "r"(a2), "r"(a3), "r"(b0), "r"(b1));
            }
        }
        __syncthreads();
    }

    // Epilogue: per-row absmax int16 quantization of y.
    // Thread holds row ra = wid*16 + lane/4 (c0,c1) and rb = ra+8 (c2,c3);
    // its cols: nt*8 + 2*(lane&3), +1.
    float m_lo = 0.f, m_hi = 0.f;
    #pragma unroll
    for (int nt = 0; nt < 16; nt++) {
        m_lo = fmaxf(m_lo, fmaxf(fabsf(acc[nt][0]), fabsf(acc[nt][1])));
        m_hi = fmaxf(m_hi, fmaxf(fabsf(acc[nt][2]), fabsf(acc[nt][3])));
    }
    // reduce across the 4 lanes of each quad (bits 0,1 of lane)
    m_lo = fmaxf(m_lo, __shfl_xor_sync(0xFFFFFFFFu, m_lo, 1));
    m_lo = fmaxf(m_lo, __shfl_xor_sync(0xFFFFFFFFu, m_lo, 2));
    m_hi = fmaxf(m_hi, __shfl_xor_sync(0xFFFFFFFFu, m_hi, 1));
    m_hi = fmaxf(m_hi, __shfl_xor_sync(0xFFFFFFFFu, m_hi, 2));

    int ra = r0 + wid * 16 + (lane >> 2);
    int rb = ra + 8;
    float inv_lo = m_lo > 0.f ? 32767.0f / m_lo : 0.f;
    float inv_hi = m_hi > 0.f ? 32767.0f / m_hi : 0.f;
    #pragma unroll
    for (int nt = 0; nt < 16; nt++) {
        int col = nt * 8 + 2 * (lane & 3);
        if (ra < cN) {
            short2 q;
            q.x = (short)__float2int_rn(acc[nt][0] * inv_lo);
            q.y = (short)__float2int_rn(acc[nt][1] * inv_lo);
            *(short2*)&g_yq[(size_t)ra * cD + col] = q;
        }
        if (rb < cN) {
            short2 q;
            q.x = (short)__float2int_rn(acc[nt][2] * inv_hi);
            q.y = (short)__float2int_rn(acc[nt][3] * inv_hi);
            *(short2*)&g_yq[(size_t)rb * cD + col] = q;
        }
    }
    if ((lane & 3) == 0) {
        if (ra < cN) g_ys[ra] = m_lo * (1.0f / 32767.0f);
        if (rb < cN) g_ys[rb] = m_hi * (1.0f / 32767.0f);
    }
}

// ---------------- fused layer1 agg + bias + leaky + dot(u) -> g_t ----------------
// warp per node: h1[node] = norm_in * sum_e norm_out[s]*y[s] + b1; t = norm_out[node]*leaky(h1).u
__global__ void k_agg_fused(const float* __restrict__ b1) {
    int gtid = blockIdx.x * blockDim.x + threadIdx.x;
    int node = gtid >> 5, lane = gtid & 31;
    if (node >= cN) return;
    const short4* __restrict__ Yq = (const short4*)g_yq;
    int beg = g_offsets[node];
    int end = g_offsets[node + 1];
    float4 acc = make_float4(0.f, 0.f, 0.f, 0.f);
    int e = beg;
    for (; e + 1 < end; e += 2) {
        int s0 = g_csr[e], s1 = g_csr[e + 1];
        float f0 = g_ys[s0] * g_norm_out[s0];
        float f1 = g_ys[s1] * g_norm_out[s1];
        short4 v0 = Yq[(size_t)s0 * 32 + lane];
        short4 v1 = Yq[(size_t)s1 * 32 + lane];
        acc.x += f0 * (float)v0.x + f1 * (float)v1.x;
        acc.y += f0 * (float)v0.y + f1 * (float)v1.y;
        acc.z += f0 * (float)v0.z + f1 * (float)v1.z;
        acc.w += f0 * (float)v0.w + f1 * (float)v1.w;
    }
    if (e < end) {
        int s0 = g_csr[e];
        float f0 = g_ys[s0] * g_norm_out[s0];
        short4 v0 = Yq[(size_t)s0 * 32 + lane];
        acc.x += f0 * (float)v0.x;
        acc.y += f0 * (float)v0.y;
        acc.z += f0 * (float)v0.z;
        acc.w += f0 * (float)v0.w;
    }
    float fi = g_norm_in[node];
    float4 bv = *(const float4*)&b1[lane * 4];
    float4 uv = *(const float4*)&g_u[lane * 4];
    float hx = acc.x * fi + bv.x; hx = hx >= 0.f ? hx : SLOPE * hx;
    float hy = acc.y * fi + bv.y; hy = hy >= 0.f ? hy : SLOPE * hy;
    float hz = acc.z * fi + bv.z; hz = hz >= 0.f ? hz : SLOPE * hz;
    float hw = acc.w * fi + bv.w; hw = hw >= 0.f ? hw : SLOPE * hw;
    float sum = hx * uv.x + hy * uv.y + hz * uv.z + hw * uv.w;
    #pragma unroll
    for (int o = 16; o; o >>= 1) sum += __shfl_xor_sync(0xFFFFFFFFu, sum, o);
    if (lane == 0) g_t[node] = sum * g_norm_out[node];
}

// ---------------- layer 2 (collapsed): scalar edge gather ----------------
__global__ void k_sgather() {
    int gtid = blockIdx.x * blockDim.x + threadIdx.x;
    int node = gtid >> 5, lane = gtid & 31;
    if (node >= cN) return;
    int beg = g_offsets[node];
    int end = g_offsets[node + 1];
    float sum = 0.f;
    for (int e = beg + lane; e < end; e += 32) sum += g_t[g_csr[e]];
    #pragma unroll
    for (int o = 16; o; o >>= 1) sum += __shfl_xor_sync(0xFFFFFFFFu, sum, o);
    if (lane == 0) g_s[node] = sum * g_norm_in[node] + g_c;
}

// ---------------- head ----------------
__global__ void k_dense1(const float* __restrict__ d1_w) {
    int c = threadIdx.x;           // blockDim = 128, active c < 100
    int rows_per_block = (cN + gridDim.x - 1) / gridDim.x;
    int r0 = blockIdx.x * rows_per_block;
    int r1 = r0 + rows_per_block; if (r1 > cN) r1 = cN;
    if (c < 100) {
        float sum = 0.f;
        for (int r = r0; r < r1; r++)
            sum += g_s[r] * d1_w[(size_t)r * 100 + c];
        atomicAdd(&g_v100[c], sum);
    }
}

__global__ void k_final(const float* __restrict__ d1_b,
                        const float* __restrict__ d2_w, const float* __restrict__ d2_b,
                        const float* __restrict__ d3_w, const float* __restrict__ d3_b,
                        float* __restrict__ out) {
    __shared__ float h100[100];
    __shared__ float h20[20];
    int t = threadIdx.x; // 128
    if (t < 100) h100[t] = g_v100[t] + d1_b[t];
    __syncthreads();
    if (t < 20) {
        float v = d2_b[t];
        #pragma unroll 4
        for (int c = 0; c < 100; c++) v += h100[c] * d2_w[c * 20 + t];
        h20[t] = v >= 0.f ? v : SLOPE * v;
    }
    __syncthreads();
    if (t < 10) {
        float o = d3_b[t];
        #pragma unroll
        for (int c = 0; c < 20; c++) o += h20[c] * d3_w[c * 10 + t];
        out[t] = o;
    }
}

// ---------------- launch ----------------
extern "C" void kernel_launch(void* const* d_in, const int* in_sizes, int n_in,
                              void* d_out, int out_size) {
    const float* x     = (const float*)d_in[0];
    const int*   src   = (const int*)d_in[1];
    const int*   dst   = (const int*)d_in[2];
    const float* W1    = (const float*)d_in[3];
    const float* b1    = (const float*)d_in[4];
    const float* W2    = (const float*)d_in[5];
    const float* b2    = (const float*)d_in[6];
    const float* agg_w = (const float*)d_in[7];
    const float* agg_b = (const float*)d_in[8];
    const float* d1_w  = (const float*)d_in[9];
    const float* d1_b  = (const float*)d_in[10];
    const float* d2_w  = (const float*)d_in[11];
    const float* d2_b  = (const float*)d_in[12];
    const float* d3_w  = (const float*)d_in[13];
    const float* d3_b  = (const float*)d_in[14];
    float* out = (float*)d_out;

    const int nb_scan = (cN + 1023) / 1024;           // 49
    const int eb = (cE + 255) / 256;                  // 6250
    const int warp_blocks = (cN * 32 + 255) / 256;    // 6250 (warp per node)
    const int gemm_blocks = (cN + 127) / 128;         // 391
    const int u_blocks = ((cD + 1) * 32 + 255) / 256; // 17

    k_zero<<<256, 256>>>();
    k_degrees<<<eb, 256>>>(src, dst);
    k_scan_block<<<nb_scan, 1024>>>();
    k_scan_add<<<nb_scan, 1024>>>();
    k_csr_fill<<<eb, 256>>>(src, dst);

    k_gemm_y<<<gemm_blocks, 256>>>(x, W1);
    k_u<<<u_blocks, 256>>>(W2, agg_w, b2, agg_b);

    k_agg_fused<<<warp_blocks, 256>>>(b1);
    k_sgather<<<warp_blocks, 256>>>();

    k_dense1<<<256, 128>>>(d1_w);
    k_final<<<1, 128>>>(d1_b, d2_w, d2_b, d3_w, d3_b, out);
}

// round 12
// speedup vs baseline: 1.8991x; 1.0749x over previous
#include <cuda_runtime.h>
#include <cuda_bf16.h>
#include <cstddef>
#include <cstdint>

#define cN 50000
#define cE 1600000
#define cD 128
#define SLOPE 0.01f

// ---------------- scratch (static device globals; no allocation) ----------------
__device__ int   g_outdeg[cN];
__device__ int   g_indeg[cN];
__device__ int   g_offsets[cN + 4];
__device__ int   g_cursor[cN];
__device__ int   g_blocksums[64];
__device__ unsigned short g_csr16[cE];
__device__ float g_norm_out[cN];
__device__ float g_norm_in[cN];
__device__ short g_yq[(size_t)cN * cD];      // int16-quantized y = x@W1 (per-row scale)
__device__ float g_ysn[cN];                  // per-row scale * norm_out for y
__device__ float g_t[cN];                    // t[r] = norm_out[r] * dot(leaky(h1[r]), u)
__device__ float g_u[cD];                    // u = W2 @ agg_w
__device__ float g_c;                        // c = b2 . agg_w + agg_b
__device__ float g_s[cN];
__device__ float g_v100[100];

// ---------------- preprocessing ----------------

__global__ void k_zero() {
    int i = blockIdx.x * blockDim.x + threadIdx.x;
    int stride = gridDim.x * blockDim.x;
    for (; i < cN; i += stride) {
        g_outdeg[i] = 0;
        g_indeg[i] = 0;
        if (i < 100) g_v100[i] = 0.0f;
    }
}

// 4 edges per thread, int4 loads (cE % 4 == 0)
__global__ void k_degrees(const int* __restrict__ src, const int* __restrict__ dst) {
    int i = blockIdx.x * blockDim.x + threadIdx.x;
    if (i < cE / 4) {
        int4 s = *(const int4*)&src[i * 4];
        int4 d = *(const int4*)&dst[i * 4];
        atomicAdd(&g_outdeg[s.x], 1); atomicAdd(&g_outdeg[s.y], 1);
        atomicAdd(&g_outdeg[s.z], 1); atomicAdd(&g_outdeg[s.w], 1);
        atomicAdd(&g_indeg[d.x], 1);  atomicAdd(&g_indeg[d.y], 1);
        atomicAdd(&g_indeg[d.z], 1);  atomicAdd(&g_indeg[d.w], 1);
    }
}

// Warp-shuffle scan: 256 threads x 4 elems = 1024/block. cN % 4 == 0.
__global__ void k_scan_block() {
    __shared__ int warp_sums[8];
    int t = threadIdx.x;
    int gid = blockIdx.x * 1024 + t * 4;
    int4 v = make_int4(0, 0, 0, 0);
    if (gid < cN) v = *(const int4*)&g_indeg[gid];
    int tsum = v.x + v.y + v.z + v.w;
    int lane = t & 31, w = t >> 5;
    int inc = tsum;
    #pragma unroll
    for (int o = 1; o < 32; o <<= 1) {
        int n = __shfl_up_sync(0xFFFFFFFFu, inc, o);
        if (lane >= o) inc += n;
    }
    if (lane == 31) warp_sums[w] = inc;
    __syncthreads();
    if (t < 32) {
        int ws = (t < 8) ? warp_sums[t] : 0;
        int wi = ws;
        #pragma unroll
        for (int o = 1; o < 8; o <<= 1) {
            int n = __shfl_up_sync(0xFFFFFFFFu, wi, o);
            if (t >= o) wi += n;
        }
        if (t < 8) warp_sums[t] = wi - ws;   // exclusive warp base
        if (t == 7) g_blocksums[blockIdx.x] = wi;  // block total
    }
    __syncthreads();
    if (gid < cN) {
        int ex = warp_sums[w] + (inc - tsum);   // block-local exclusive for this thread
        int4 o;
        o.x = ex;
        o.y = ex + v.x;
        o.z = ex + v.x + v.y;
        o.w = ex + v.x + v.y + v.z;
        *(int4*)&g_offsets[gid] = o;
    }
}

// add block base + cursor + norms (vectorized).
// Base covers up to 64 prior blocks: 2 slots per lane (nb_scan = 49 <= 64).
__global__ void k_scan_add() {
    __shared__ int s_base;
    if (threadIdx.x < 32) {
        int t = threadIdx.x;
        int v = 0;
        if (t      < blockIdx.x) v += g_blocksums[t];
        if (t + 32 < blockIdx.x) v += g_blocksums[t + 32];
        #pragma unroll
        for (int o = 16; o; o >>= 1) v += __shfl_xor_sync(0xFFFFFFFFu, v, o);
        if (t == 0) s_base = v;
    }
    __syncthreads();
    int gid = blockIdx.x * 1024 + threadIdx.x * 4;
    if (gid < cN) {
        int4 o = *(const int4*)&g_offsets[gid];
        o.x += s_base; o.y += s_base; o.z += s_base; o.w += s_base;
        *(int4*)&g_offsets[gid] = o;
        *(int4*)&g_cursor[gid] = o;
        int4 od = *(const int4*)&g_outdeg[gid];
        int4 id = *(const int4*)&g_indeg[gid];
        float4 no, ni;
        no.x = rsqrtf(fmaxf((float)od.x, 1.0f)); no.y = rsqrtf(fmaxf((float)od.y, 1.0f));
        no.z = rsqrtf(fmaxf((float)od.z, 1.0f)); no.w = rsqrtf(fmaxf((float)od.w, 1.0f));
        ni.x = rsqrtf(fmaxf((float)id.x, 1.0f)); ni.y = rsqrtf(fmaxf((float)id.y, 1.0f));
        ni.z = rsqrtf(fmaxf((float)id.z, 1.0f)); ni.w = rsqrtf(fmaxf((float)id.w, 1.0f));
        *(float4*)&g_norm_out[gid] = no;
        *(float4*)&g_norm_in[gid] = ni;
    }
    if (gid == 0) g_offsets[cN] = cE;
}

__global__ void k_csr_fill(const int* __restrict__ src, const int* __restrict__ dst) {
    int i = blockIdx.x * blockDim.x + threadIdx.x;
    if (i < cE) {
        int p = atomicAdd(&g_cursor[dst[i]], 1);
        g_csr16[p] = (unsigned short)src[i];
    }
}

// u = W2 @ agg_w  (warp per row), c = b2 . agg_w + agg_b
__global__ void k_u(const float* __restrict__ W2, const float* __restrict__ agg_w,
                    const float* __restrict__ b2, const float* __restrict__ agg_b) {
    int gtid = blockIdx.x * blockDim.x + threadIdx.x;
    int w = gtid >> 5, lane = gtid & 31;
    if (w < cD) {
        float sum = 0.f;
        #pragma unroll
        for (int c = lane; c < cD; c += 32) sum += W2[(size_t)w * cD + c] * agg_w[c];
        #pragma unroll
        for (int o = 16; o; o >>= 1) sum += __shfl_xor_sync(0xFFFFFFFFu, sum, o);
        if (lane == 0) g_u[w] = sum;
    } else if (w == cD) {
        float sum = 0.f;
        #pragma unroll
        for (int c = lane; c < cD; c += 32) sum += b2[c] * agg_w[c];
        #pragma unroll
        for (int o = 16; o; o >>= 1) sum += __shfl_xor_sync(0xFFFFFFFFu, sum, o);
        if (lane == 0) g_c = sum + agg_b[0];
    }
}

// ---------------- y = x @ W1 via tf32 tensor cores, int16-quantized epilogue ----------------
__device__ __forceinline__ uint32_t f2tf32(float f) {
    uint32_t u;
    asm("cvt.rna.tf32.f32 %0, %1;" : "=r"(u) : "f"(f));
    return u;
}

__global__ __launch_bounds__(256) void k_gemm_y(const float* __restrict__ x,
                                                const float* __restrict__ W1) {
    __shared__ uint32_t As[128 * 36];
    __shared__ uint32_t Ws[32 * 132];
    int tid = threadIdx.x;
    int wid = tid >> 5;
    int lane = tid & 31;
    int r0 = blockIdx.x * 128;

    float acc[16][4];
    #pragma unroll
    for (int nt = 0; nt < 16; nt++)
        #pragma unroll
        for (int j = 0; j < 4; j++) acc[nt][j] = 0.f;

    for (int k0 = 0; k0 < cD; k0 += 32) {
        #pragma unroll
        for (int i = 0; i < 4; i++) {
            int idx = tid + 256 * i;
            int row = idx >> 3, c4 = idx & 7;
            int gr = r0 + row;
            float4 v = make_float4(0.f, 0.f, 0.f, 0.f);
            if (gr < cN) v = *(const float4*)&x[(size_t)gr * cD + k0 + c4 * 4];
            uint32_t* p = &As[row * 36 + c4 * 4];
            p[0] = f2tf32(v.x); p[1] = f2tf32(v.y); p[2] = f2tf32(v.z); p[3] = f2tf32(v.w);
        }
        #pragma unroll
        for (int i = 0; i < 4; i++) {
            int idx = tid + 256 * i;
            int row = idx >> 5, c4 = idx & 31;
            float4 v = *(const float4*)&W1[(size_t)(k0 + row) * cD + c4 * 4];
            uint32_t* p = &Ws[row * 132 + c4 * 4];
            p[0] = f2tf32(v.x); p[1] = f2tf32(v.y); p[2] = f2tf32(v.z); p[3] = f2tf32(v.w);
        }
        __syncthreads();
        #pragma unroll
        for (int ks = 0; ks < 4; ks++) {
            int ar = wid * 16 + (lane >> 2);
            int ac = ks * 8 + (lane & 3);
            uint32_t a0 = As[ar * 36 + ac];
            uint32_t a1 = As[(ar + 8) * 36 + ac];
            uint32_t a2 = As[ar * 36 + ac + 4];
            uint32_t a3 = As[(ar + 8) * 36 + ac + 4];
            int bk = ks * 8 + (lane & 3);
            int bn0 = (lane >> 2);
            #pragma unroll
            for (int nt = 0; nt < 16; nt++) {
                uint32_t b0 = Ws[bk * 132 + nt * 8 + bn0];
                uint32_t b1 = Ws[(bk + 4) * 132 + nt * 8 + bn0];
                asm volatile(
                    "mma.sync.aligned.m16n8k8.row.col.f32.tf32.tf32.f32 "
                    "{%0,%1,%2,%3}, {%4,%5,%6,%7}, {%8,%9}, {%0,%1,%2,%3};"
                    : "+f"(acc[nt][0]), "+f"(acc[nt][1]), "+f"(acc[nt][2]), "+f"(acc[nt][3])
                    : "r"(a0), "r"(a1), "r"(a2), "r"(a3), "r"(b0), "r"(b1));
            }
        }
        __syncthreads();
    }

    // Epilogue: per-row absmax int16 quantization; scale folds norm_out (safe: serial stream).
    float m_lo = 0.f, m_hi = 0.f;
    #pragma unroll
    for (int nt = 0; nt < 16; nt++) {
        m_lo = fmaxf(m_lo, fmaxf(fabsf(acc[nt][0]), fabsf(acc[nt][1])));
        m_hi = fmaxf(m_hi, fmaxf(fabsf(acc[nt][2]), fabsf(acc[nt][3])));
    }
    m_lo = fmaxf(m_lo, __shfl_xor_sync(0xFFFFFFFFu, m_lo, 1));
    m_lo = fmaxf(m_lo, __shfl_xor_sync(0xFFFFFFFFu, m_lo, 2));
    m_hi = fmaxf(m_hi, __shfl_xor_sync(0xFFFFFFFFu, m_hi, 1));
    m_hi = fmaxf(m_hi, __shfl_xor_sync(0xFFFFFFFFu, m_hi, 2));

    int ra = r0 + wid * 16 + (lane >> 2);
    int rb = ra + 8;
    float inv_lo = m_lo > 0.f ? 32767.0f / m_lo : 0.f;
    float inv_hi = m_hi > 0.f ? 32767.0f / m_hi : 0.f;
    #pragma unroll
    for (int nt = 0; nt < 16; nt++) {
        int col = nt * 8 + 2 * (lane & 3);
        if (ra < cN) {
            short2 q;
            q.x = (short)__float2int_rn(acc[nt][0] * inv_lo);
            q.y = (short)__float2int_rn(acc[nt][1] * inv_lo);
            *(short2*)&g_yq[(size_t)ra * cD + col] = q;
        }
        if (rb < cN) {
            short2 q;
            q.x = (short)__float2int_rn(acc[nt][2] * inv_hi);
            q.y = (short)__float2int_rn(acc[nt][3] * inv_hi);
            *(short2*)&g_yq[(size_t)rb * cD + col] = q;
        }
    }
    if ((lane & 3) == 0) {
        if (ra < cN) g_ysn[ra] = m_lo * (1.0f / 32767.0f) * g_norm_out[ra];
        if (rb < cN) g_ysn[rb] = m_hi * (1.0f / 32767.0f) * g_norm_out[rb];
    }
}

// ---------------- fused layer1 agg + bias + leaky + dot(u) -> g_t ----------------
// warp per node, int16 rows (short4 = 8B per lane per edge), one scalar load per edge.
__global__ void k_agg_fused(const float* __restrict__ b1) {
    int gtid = blockIdx.x * blockDim.x + threadIdx.x;
    int node = gtid >> 5, lane = gtid & 31;
    if (node >= cN) return;
    const short4* __restrict__ Yq = (const short4*)g_yq;
    int beg = g_offsets[node];
    int end = g_offsets[node + 1];
    float4 acc = make_float4(0.f, 0.f, 0.f, 0.f);
    int e = beg;
    for (; e + 1 < end; e += 2) {
        int s0 = g_csr16[e], s1 = g_csr16[e + 1];
        float f0 = g_ysn[s0], f1 = g_ysn[s1];
        short4 v0 = Yq[(size_t)s0 * 32 + lane];
        short4 v1 = Yq[(size_t)s1 * 32 + lane];
        acc.x += f0 * (float)v0.x + f1 * (float)v1.x;
        acc.y += f0 * (float)v0.y + f1 * (float)v1.y;
        acc.z += f0 * (float)v0.z + f1 * (float)v1.z;
        acc.w += f0 * (float)v0.w + f1 * (float)v1.w;
    }
    if (e < end) {
        int s0 = g_csr16[e];
        float f0 = g_ysn[s0];
        short4 v0 = Yq[(size_t)s0 * 32 + lane];
        acc.x += f0 * (float)v0.x;
        acc.y += f0 * (float)v0.y;
        acc.z += f0 * (float)v0.z;
        acc.w += f0 * (float)v0.w;
    }
    float fi = g_norm_in[node];
    float4 bv = *(const float4*)&b1[lane * 4];
    float4 uv = *(const float4*)&g_u[lane * 4];
    float hx = acc.x * fi + bv.x; hx = hx >= 0.f ? hx : SLOPE * hx;
    float hy = acc.y * fi + bv.y; hy = hy >= 0.f ? hy : SLOPE * hy;
    float hz = acc.z * fi + bv.z; hz = hz >= 0.f ? hz : SLOPE * hz;
    float hw = acc.w * fi + bv.w; hw = hw >= 0.f ? hw : SLOPE * hw;
    float sum = hx * uv.x + hy * uv.y + hz * uv.z + hw * uv.w;
    #pragma unroll
    for (int o = 16; o; o >>= 1) sum += __shfl_xor_sync(0xFFFFFFFFu, sum, o);
    if (lane == 0) g_t[node] = sum * g_norm_out[node];
}

// ---------------- layer 2 (collapsed): scalar edge gather ----------------
__global__ void k_sgather() {
    int gtid = blockIdx.x * blockDim.x + threadIdx.x;
    int node = gtid >> 5, lane = gtid & 31;
    if (node >= cN) return;
    int beg = g_offsets[node];
    int end = g_offsets[node + 1];
    float sum = 0.f;
    for (int e = beg + lane; e < end; e += 32) sum += g_t[g_csr16[e]];
    #pragma unroll
    for (int o = 16; o; o >>= 1) sum += __shfl_xor_sync(0xFFFFFFFFu, sum, o);
    if (lane == 0) g_s[node] = sum * g_norm_in[node] + g_c;
}

// ---------------- head ----------------
__global__ void k_dense1(const float* __restrict__ d1_w) {
    int c = threadIdx.x;           // blockDim = 128, active c < 100
    int rows_per_block = (cN + gridDim.x - 1) / gridDim.x;
    int r0 = blockIdx.x * rows_per_block;
    int r1 = r0 + rows_per_block; if (r1 > cN) r1 = cN;
    if (c < 100) {
        float sum = 0.f;
        for (int r = r0; r < r1; r++)
            sum += g_s[r] * d1_w[(size_t)r * 100 + c];
        atomicAdd(&g_v100[c], sum);
    }
}

__global__ void k_final(const float* __restrict__ d1_b,
                        const float* __restrict__ d2_w, const float* __restrict__ d2_b,
                        const float* __restrict__ d3_w, const float* __restrict__ d3_b,
                        float* __restrict__ out) {
    __shared__ float h100[100];
    __shared__ float h20[20];
    int t = threadIdx.x; // 128
    if (t < 100) h100[t] = g_v100[t] + d1_b[t];
    __syncthreads();
    if (t < 20) {
        float v = d2_b[t];
        #pragma unroll 4
        for (int c = 0; c < 100; c++) v += h100[c] * d2_w[c * 20 + t];
        h20[t] = v >= 0.f ? v : SLOPE * v;
    }
    __syncthreads();
    if (t < 10) {
        float o = d3_b[t];
        #pragma unroll
        for (int c = 0; c < 20; c++) o += h20[c] * d3_w[c * 10 + t];
        out[t] = o;
    }
}

// ---------------- launch ----------------
extern "C" void kernel_launch(void* const* d_in, const int* in_sizes, int n_in,
                              void* d_out, int out_size) {
    const float* x     = (const float*)d_in[0];
    const int*   src   = (const int*)d_in[1];
    const int*   dst   = (const int*)d_in[2];
    const float* W1    = (const float*)d_in[3];
    const float* b1    = (const float*)d_in[4];
    const float* W2    = (const float*)d_in[5];
    const float* b2    = (const float*)d_in[6];
    const float* agg_w = (const float*)d_in[7];
    const float* agg_b = (const float*)d_in[8];
    const float* d1_w  = (const float*)d_in[9];
    const float* d1_b  = (const float*)d_in[10];
    const float* d2_w  = (const float*)d_in[11];
    const float* d2_b  = (const float*)d_in[12];
    const float* d3_w  = (const float*)d_in[13];
    const float* d3_b  = (const float*)d_in[14];
    float* out = (float*)d_out;

    const int nb_scan = (cN + 1023) / 1024;           // 49
    const int eb = (cE + 255) / 256;                  // 6250
    const int eb4 = (cE / 4 + 255) / 256;             // 1563
    const int warp_blocks = (cN * 32 + 255) / 256;    // 6250 (warp per node)
    const int gemm_blocks = (cN + 127) / 128;         // 391
    const int u_blocks = ((cD + 1) * 32 + 255) / 256; // 17

    k_zero<<<256, 256>>>();
    k_degrees<<<eb4, 256>>>(src, dst);
    k_scan_block<<<nb_scan, 256>>>();
    k_scan_add<<<nb_scan, 256>>>();
    k_csr_fill<<<eb, 256>>>(src, dst);

    k_gemm_y<<<gemm_blocks, 256>>>(x, W1);
    k_u<<<u_blocks, 256>>>(W2, agg_w, b2, agg_b);

    k_agg_fused<<<warp_blocks, 256>>>(b1);
    k_sgather<<<warp_blocks, 256>>>();

    k_dense1<<<512, 128>>>(d1_w);
    k_final<<<1, 128>>>(d1_b, d2_w, d2_b, d3_w, d3_b, out);
}

// round 13
// speedup vs baseline: 2.0903x; 1.1007x over previous
#include <cuda_runtime.h>
#include <cuda_bf16.h>
#include <cstddef>
#include <cstdint>

#define cN 50000
#define cE 1600000
#define cD 128
#define SLOPE 0.01f

#define GEMM_BLOCKS 391   // (cN + 127) / 128
#define DEG_BLOCKS 1563   // (cE/4 + 255) / 256
#define U_BLOCKS 17       // ((cD+1)*32 + 255) / 256

// ---------------- scratch (static device globals; no allocation) ----------------
__device__ int   g_outdeg[cN];      // zeroed by k_csr_fill each call (zero-init first call)
__device__ int   g_indeg[cN];
__device__ int   g_offsets[cN + 4];
__device__ int   g_cursor[cN];
__device__ int   g_blocksums[64];
__device__ unsigned short g_csr16[cE];
__device__ float g_norm_out[cN];
__device__ float g_norm_in[cN];
__device__ short g_yq[(size_t)cN * cD];      // int16-quantized y = x@W1 (per-row scale)
__device__ float g_ysn[cN];                  // raw scale from gemm; *= norm_out in scan_add
__device__ float g_t[cN];                    // t[r] = norm_out[r] * dot(leaky(h1[r]), u)
__device__ float g_u[cD];                    // u = W2 @ agg_w
__device__ float g_c;                        // c = b2 . agg_w + agg_b
__device__ float g_s[cN];
__device__ float g_v100[100];                // zeroed by k_final each call

__device__ __forceinline__ uint32_t f2tf32(float f) {
    uint32_t u;
    asm("cvt.rna.tf32.f32 %0, %1;" : "=r"(u) : "f"(f));
    return u;
}

// ---------------- fused launch 1: tf32 GEMM (y=x@W1) || degree atomics || u=W2@agg_w ----
// GEMM has no graph dependency (norm_out fold deferred to k_scan_add), so degree
// counting and the u-vector run concurrently on other SMs under the GEMM.
__global__ __launch_bounds__(256) void k_fused1(
    const float* __restrict__ x, const float* __restrict__ W1,
    const int* __restrict__ src, const int* __restrict__ dst,
    const float* __restrict__ W2, const float* __restrict__ agg_w,
    const float* __restrict__ b2, const float* __restrict__ agg_b)
{
    __shared__ uint32_t As[128 * 36];
    __shared__ uint32_t Ws[32 * 132];
    int tid = threadIdx.x;

    if (blockIdx.x >= GEMM_BLOCKS + DEG_BLOCKS) {
        // ---- u part: u = W2 @ agg_w (warp per row), c = b2.agg_w + agg_b ----
        int gtid = (blockIdx.x - GEMM_BLOCKS - DEG_BLOCKS) * 256 + tid;
        int w = gtid >> 5, lane = gtid & 31;
        if (w < cD) {
            float sum = 0.f;
            #pragma unroll
            for (int c = lane; c < cD; c += 32) sum += W2[(size_t)w * cD + c] * agg_w[c];
            #pragma unroll
            for (int o = 16; o; o >>= 1) sum += __shfl_xor_sync(0xFFFFFFFFu, sum, o);
            if (lane == 0) g_u[w] = sum;
        } else if (w == cD) {
            float sum = 0.f;
            #pragma unroll
            for (int c = lane; c < cD; c += 32) sum += b2[c] * agg_w[c];
            #pragma unroll
            for (int o = 16; o; o >>= 1) sum += __shfl_xor_sync(0xFFFFFFFFu, sum, o);
            if (lane == 0) g_c = sum + agg_b[0];
        }
        return;
    }

    if (blockIdx.x >= GEMM_BLOCKS) {
        // ---- degrees part: 4 edges per thread, int4 loads (cE % 4 == 0) ----
        int i = (blockIdx.x - GEMM_BLOCKS) * 256 + tid;
        if (i < cE / 4) {
            int4 s = *(const int4*)&src[i * 4];
            int4 d = *(const int4*)&dst[i * 4];
            atomicAdd(&g_outdeg[s.x], 1); atomicAdd(&g_outdeg[s.y], 1);
            atomicAdd(&g_outdeg[s.z], 1); atomicAdd(&g_outdeg[s.w], 1);
            atomicAdd(&g_indeg[d.x], 1);  atomicAdd(&g_indeg[d.y], 1);
            atomicAdd(&g_indeg[d.z], 1);  atomicAdd(&g_indeg[d.w], 1);
        }
        return;
    }

    // ---- GEMM part: 128x128 tile of y = x @ W1, int16-quantized epilogue ----
    int wid = tid >> 5;
    int lane = tid & 31;
    int r0 = blockIdx.x * 128;

    float acc[16][4];
    #pragma unroll
    for (int nt = 0; nt < 16; nt++)
        #pragma unroll
        for (int j = 0; j < 4; j++) acc[nt][j] = 0.f;

    for (int k0 = 0; k0 < cD; k0 += 32) {
        #pragma unroll
        for (int i = 0; i < 4; i++) {
            int idx = tid + 256 * i;
            int row = idx >> 3, c4 = idx & 7;
            int gr = r0 + row;
            float4 v = make_float4(0.f, 0.f, 0.f, 0.f);
            if (gr < cN) v = *(const float4*)&x[(size_t)gr * cD + k0 + c4 * 4];
            uint32_t* p = &As[row * 36 + c4 * 4];
            p[0] = f2tf32(v.x); p[1] = f2tf32(v.y); p[2] = f2tf32(v.z); p[3] = f2tf32(v.w);
        }
        #pragma unroll
        for (int i = 0; i < 4; i++) {
            int idx = tid + 256 * i;
            int row = idx >> 5, c4 = idx & 31;
            float4 v = *(const float4*)&W1[(size_t)(k0 + row) * cD + c4 * 4];
            uint32_t* p = &Ws[row * 132 + c4 * 4];
            p[0] = f2tf32(v.x); p[1] = f2tf32(v.y); p[2] = f2tf32(v.z); p[3] = f2tf32(v.w);
        }
        __syncthreads();
        #pragma unroll
        for (int ks = 0; ks < 4; ks++) {
            int ar = wid * 16 + (lane >> 2);
            int ac = ks * 8 + (lane & 3);
            uint32_t a0 = As[ar * 36 + ac];
            uint32_t a1 = As[(ar + 8) * 36 + ac];
            uint32_t a2 = As[ar * 36 + ac + 4];
            uint32_t a3 = As[(ar + 8) * 36 + ac + 4];
            int bk = ks * 8 + (lane & 3);
            int bn0 = (lane >> 2);
            #pragma unroll
            for (int nt = 0; nt < 16; nt++) {
                uint32_t b0 = Ws[bk * 132 + nt * 8 + bn0];
                uint32_t b1 = Ws[(bk + 4) * 132 + nt * 8 + bn0];
                asm volatile(
                    "mma.sync.aligned.m16n8k8.row.col.f32.tf32.tf32.f32 "
                    "{%0,%1,%2,%3}, {%4,%5,%6,%7}, {%8,%9}, {%0,%1,%2,%3};"
                    : "+f"(acc[nt][0]), "+f"(acc[nt][1]), "+f"(acc[nt][2]), "+f"(acc[nt][3])
                    : "r"(a0), "r"(a1), "r"(a2), "r"(a3), "r"(b0), "r"(b1));
            }
        }
        __syncthreads();
    }

    // Epilogue: per-row absmax int16 quantization; RAW scale (norm_out folded later).
    float m_lo = 0.f, m_hi = 0.f;
    #pragma unroll
    for (int nt = 0; nt < 16; nt++) {
        m_lo = fmaxf(m_lo, fmaxf(fabsf(acc[nt][0]), fabsf(acc[nt][1])));
        m_hi = fmaxf(m_hi, fmaxf(fabsf(acc[nt][2]), fabsf(acc[nt][3])));
    }
    m_lo = fmaxf(m_lo, __shfl_xor_sync(0xFFFFFFFFu, m_lo, 1));
    m_lo = fmaxf(m_lo, __shfl_xor_sync(0xFFFFFFFFu, m_lo, 2));
    m_hi = fmaxf(m_hi, __shfl_xor_sync(0xFFFFFFFFu, m_hi, 1));
    m_hi = fmaxf(m_hi, __shfl_xor_sync(0xFFFFFFFFu, m_hi, 2));

    int ra = r0 + wid * 16 + (lane >> 2);
    int rb = ra + 8;
    float inv_lo = m_lo > 0.f ? 32767.0f / m_lo : 0.f;
    float inv_hi = m_hi > 0.f ? 32767.0f / m_hi : 0.f;
    #pragma unroll
    for (int nt = 0; nt < 16; nt++) {
        int col = nt * 8 + 2 * (lane & 3);
        if (ra < cN) {
            short2 q;
            q.x = (short)__float2int_rn(acc[nt][0] * inv_lo);
            q.y = (short)__float2int_rn(acc[nt][1] * inv_lo);
            *(short2*)&g_yq[(size_t)ra * cD + col] = q;
        }
        if (rb < cN) {
            short2 q;
            q.x = (short)__float2int_rn(acc[nt][2] * inv_hi);
            q.y = (short)__float2int_rn(acc[nt][3] * inv_hi);
            *(short2*)&g_yq[(size_t)rb * cD + col] = q;
        }
    }
    if ((lane & 3) == 0) {
        if (ra < cN) g_ysn[ra] = m_lo * (1.0f / 32767.0f);
        if (rb < cN) g_ysn[rb] = m_hi * (1.0f / 32767.0f);
    }
}

// ---------------- scans ----------------
// Warp-shuffle scan: 256 threads x 4 elems = 1024/block. cN % 4 == 0.
__global__ void k_scan_block() {
    __shared__ int warp_sums[8];
    int t = threadIdx.x;
    int gid = blockIdx.x * 1024 + t * 4;
    int4 v = make_int4(0, 0, 0, 0);
    if (gid < cN) v = *(const int4*)&g_indeg[gid];
    int tsum = v.x + v.y + v.z + v.w;
    int lane = t & 31, w = t >> 5;
    int inc = tsum;
    #pragma unroll
    for (int o = 1; o < 32; o <<= 1) {
        int n = __shfl_up_sync(0xFFFFFFFFu, inc, o);
        if (lane >= o) inc += n;
    }
    if (lane == 31) warp_sums[w] = inc;
    __syncthreads();
    if (t < 32) {
        int ws = (t < 8) ? warp_sums[t] : 0;
        int wi = ws;
        #pragma unroll
        for (int o = 1; o < 8; o <<= 1) {
            int n = __shfl_up_sync(0xFFFFFFFFu, wi, o);
            if (t >= o) wi += n;
        }
        if (t < 8) warp_sums[t] = wi - ws;   // exclusive warp base
        if (t == 7) g_blocksums[blockIdx.x] = wi;  // block total
    }
    __syncthreads();
    if (gid < cN) {
        int ex = warp_sums[w] + (inc - tsum);
        int4 o;
        o.x = ex;
        o.y = ex + v.x;
        o.z = ex + v.x + v.y;
        o.w = ex + v.x + v.y + v.z;
        *(int4*)&g_offsets[gid] = o;
    }
}

// block base + cursor + norms + fold norm_out into ysn (vectorized).
__global__ void k_scan_add() {
    __shared__ int s_base;
    if (threadIdx.x < 32) {
        int t = threadIdx.x;
        int v = 0;
        if (t      < blockIdx.x) v += g_blocksums[t];
        if (t + 32 < blockIdx.x) v += g_blocksums[t + 32];
        #pragma unroll
        for (int o = 16; o; o >>= 1) v += __shfl_xor_sync(0xFFFFFFFFu, v, o);
        if (t == 0) s_base = v;
    }
    __syncthreads();
    int gid = blockIdx.x * 1024 + threadIdx.x * 4;
    if (gid < cN) {
        int4 o = *(const int4*)&g_offsets[gid];
        o.x += s_base; o.y += s_base; o.z += s_base; o.w += s_base;
        *(int4*)&g_offsets[gid] = o;
        *(int4*)&g_cursor[gid] = o;
        int4 od = *(const int4*)&g_outdeg[gid];
        int4 id = *(const int4*)&g_indeg[gid];
        float4 no, ni;
        no.x = rsqrtf(fmaxf((float)od.x, 1.0f)); no.y = rsqrtf(fmaxf((float)od.y, 1.0f));
        no.z = rsqrtf(fmaxf((float)od.z, 1.0f)); no.w = rsqrtf(fmaxf((float)od.w, 1.0f));
        ni.x = rsqrtf(fmaxf((float)id.x, 1.0f)); ni.y = rsqrtf(fmaxf((float)id.y, 1.0f));
        ni.z = rsqrtf(fmaxf((float)id.z, 1.0f)); ni.w = rsqrtf(fmaxf((float)id.w, 1.0f));
        *(float4*)&g_norm_out[gid] = no;
        *(float4*)&g_norm_in[gid] = ni;
        float4 ys = *(const float4*)&g_ysn[gid];
        ys.x *= no.x; ys.y *= no.y; ys.z *= no.z; ys.w *= no.w;
        *(float4*)&g_ysn[gid] = ys;
    }
    if (gid == 0) g_offsets[cN] = cE;
}

// csr fill + recycle: zero degree arrays for the next call (they are dead now).
__global__ void k_csr_fill(const int* __restrict__ src, const int* __restrict__ dst) {
    int i = blockIdx.x * blockDim.x + threadIdx.x;
    if (i < cE) {
        int p = atomicAdd(&g_cursor[dst[i]], 1);
        g_csr16[p] = (unsigned short)src[i];
    }
    if (i < cN) {
        g_outdeg[i] = 0;
        g_indeg[i] = 0;
    }
}

// ---------------- fused layer1 agg + bias + leaky + dot(u) -> g_t ----------------
// warp per node, int16 rows (short4 = 8B per lane per edge), one scalar load per edge.
__global__ void k_agg_fused(const float* __restrict__ b1) {
    int gtid = blockIdx.x * blockDim.x + threadIdx.x;
    int node = gtid >> 5, lane = gtid & 31;
    if (node >= cN) return;
    const short4* __restrict__ Yq = (const short4*)g_yq;
    int beg = g_offsets[node];
    int end = g_offsets[node + 1];
    float4 acc = make_float4(0.f, 0.f, 0.f, 0.f);
    int e = beg;
    for (; e + 3 < end; e += 4) {
        int s0 = g_csr16[e], s1 = g_csr16[e + 1], s2 = g_csr16[e + 2], s3 = g_csr16[e + 3];
        float f0 = g_ysn[s0], f1 = g_ysn[s1], f2 = g_ysn[s2], f3 = g_ysn[s3];
        short4 v0 = Yq[(size_t)s0 * 32 + lane];
        short4 v1 = Yq[(size_t)s1 * 32 + lane];
        short4 v2 = Yq[(size_t)s2 * 32 + lane];
        short4 v3 = Yq[(size_t)s3 * 32 + lane];
        acc.x += f0 * (float)v0.x + f1 * (float)v1.x + f2 * (float)v2.x + f3 * (float)v3.x;
        acc.y += f0 * (float)v0.y + f1 * (float)v1.y + f2 * (float)v2.y + f3 * (float)v3.y;
        acc.z += f0 * (float)v0.z + f1 * (float)v1.z + f2 * (float)v2.z + f3 * (float)v3.z;
        acc.w += f0 * (float)v0.w + f1 * (float)v1.w + f2 * (float)v2.w + f3 * (float)v3.w;
    }
    for (; e < end; e++) {
        int s0 = g_csr16[e];
        float f0 = g_ysn[s0];
        short4 v0 = Yq[(size_t)s0 * 32 + lane];
        acc.x += f0 * (float)v0.x;
        acc.y += f0 * (float)v0.y;
        acc.z += f0 * (float)v0.z;
        acc.w += f0 * (float)v0.w;
    }
    float fi = g_norm_in[node];
    float4 bv = *(const float4*)&b1[lane * 4];
    float4 uv = *(const float4*)&g_u[lane * 4];
    float hx = acc.x * fi + bv.x; hx = hx >= 0.f ? hx : SLOPE * hx;
    float hy = acc.y * fi + bv.y; hy = hy >= 0.f ? hy : SLOPE * hy;
    float hz = acc.z * fi + bv.z; hz = hz >= 0.f ? hz : SLOPE * hz;
    float hw = acc.w * fi + bv.w; hw = hw >= 0.f ? hw : SLOPE * hw;
    float sum = hx * uv.x + hy * uv.y + hz * uv.z + hw * uv.w;
    #pragma unroll
    for (int o = 16; o; o >>= 1) sum += __shfl_xor_sync(0xFFFFFFFFu, sum, o);
    if (lane == 0) g_t[node] = sum * g_norm_out[node];
}

// ---------------- layer 2 (collapsed): scalar edge gather ----------------
__global__ void k_sgather() {
    int gtid = blockIdx.x * blockDim.x + threadIdx.x;
    int node = gtid >> 5, lane = gtid & 31;
    if (node >= cN) return;
    int beg = g_offsets[node];
    int end = g_offsets[node + 1];
    float sum = 0.f;
    for (int e = beg + lane; e < end; e += 32) sum += g_t[g_csr16[e]];
    #pragma unroll
    for (int o = 16; o; o >>= 1) sum += __shfl_xor_sync(0xFFFFFFFFu, sum, o);
    if (lane == 0) g_s[node] = sum * g_norm_in[node] + g_c;
}

// ---------------- head ----------------
__global__ void k_dense1(const float* __restrict__ d1_w) {
    int c = threadIdx.x;           // blockDim = 128, active c < 100
    int rows_per_block = (cN + gridDim.x - 1) / gridDim.x;
    int r0 = blockIdx.x * rows_per_block;
    int r1 = r0 + rows_per_block; if (r1 > cN) r1 = cN;
    if (c < 100) {
        float sum = 0.f;
        for (int r = r0; r < r1; r++)
            sum += g_s[r] * d1_w[(size_t)r * 100 + c];
        atomicAdd(&g_v100[c], sum);
    }
}

__global__ void k_final(const float* __restrict__ d1_b,
                        const float* __restrict__ d2_w, const float* __restrict__ d2_b,
                        const float* __restrict__ d3_w, const float* __restrict__ d3_b,
                        float* __restrict__ out) {
    __shared__ float h100[100];
    __shared__ float h20[20];
    int t = threadIdx.x; // 128
    if (t < 100) h100[t] = g_v100[t] + d1_b[t];
    __syncthreads();
    if (t < 100) g_v100[t] = 0.0f;   // recycle for next call
    if (t < 20) {
        float v = d2_b[t];
        #pragma unroll 4
        for (int c = 0; c < 100; c++) v += h100[c] * d2_w[c * 20 + t];
        h20[t] = v >= 0.f ? v : SLOPE * v;
    }
    __syncthreads();
    if (t < 10) {
        float o = d3_b[t];
        #pragma unroll
        for (int c = 0; c < 20; c++) o += h20[c] * d3_w[c * 10 + t];
        out[t] = o;
    }
}

// ---------------- launch ----------------
extern "C" void kernel_launch(void* const* d_in, const int* in_sizes, int n_in,
                              void* d_out, int out_size) {
    const float* x     = (const float*)d_in[0];
    const int*   src   = (const int*)d_in[1];
    const int*   dst   = (const int*)d_in[2];
    const float* W1    = (const float*)d_in[3];
    const float* b1    = (const float*)d_in[4];
    const float* W2    = (const float*)d_in[5];
    const float* b2    = (const float*)d_in[6];
    const float* agg_w = (const float*)d_in[7];
    const float* agg_b = (const float*)d_in[8];
    const float* d1_w  = (const float*)d_in[9];
    const float* d1_b  = (const float*)d_in[10];
    const float* d2_w  = (const float*)d_in[11];
    const float* d2_b  = (const float*)d_in[12];
    const float* d3_w  = (const float*)d_in[13];
    const float* d3_b  = (const float*)d_in[14];
    float* out = (float*)d_out;

    const int nb_scan = (cN + 1023) / 1024;           // 49
    const int eb = (cE + 255) / 256;                  // 6250
    const int warp_blocks = (cN * 32 + 255) / 256;    // 6250 (warp per node)
    const int fused_blocks = GEMM_BLOCKS + DEG_BLOCKS + U_BLOCKS;  // 1971

    k_fused1<<<fused_blocks, 256>>>(x, W1, src, dst, W2, agg_w, b2, agg_b);
    k_scan_block<<<nb_scan, 256>>>();
    k_scan_add<<<nb_scan, 256>>>();
    k_csr_fill<<<eb, 256>>>(src, dst);

    k_agg_fused<<<warp_blocks, 256>>>(b1);
    k_sgather<<<warp_blocks, 256>>>();

    k_dense1<<<512, 128>>>(d1_w);
    k_final<<<1, 128>>>(d1_b, d2_w, d2_b, d3_w, d3_b, out);
}